// round 11
// baseline (speedup 1.0000x reference)
#include <cuda_runtime.h>
#include <math.h>
#include <stdint.h>

// ---------------- problem constants ----------------
#define NTOK   16384        // 4 * 4096
#define DIM    1024
#define HID    2048
#define HV2    4096         // 2*HID
#define QK     128
#define G      256
#define NGRP   64           // 4 batches * 16 groups
#define NB     4
#define NGPB   16
#define LN_EPS 1e-5f

// ---------------- scratch (device globals) ----------------
__device__ float g_normed[(size_t)NTOK * DIM];
__device__ float g_vT    [(size_t)NGRP * HID * G];   // v transposed per group: [g][e][t]
__device__ float g_gate  [(size_t)NTOK * HID];
__device__ float g_qq    [(size_t)NTOK * QK];        // [g][t][d] (tf32)
__device__ float g_lq    [(size_t)NTOK * QK];
__device__ float g_qkh   [(size_t)NTOK * QK];        // (tf32)
__device__ float g_lkT   [(size_t)NGRP * QK * G];    // lin_k transposed: [g][d][t]
__device__ float g_attn  [(size_t)NGRP * G * G];
__device__ float g_ao    [(size_t)NTOK * HID];
__device__ float g_linkv [(size_t)NGRP * HID * QK];  // [g][e][d]
__device__ float g_WhT   [(size_t)HV2 * DIM];
__device__ float g_WqkT  [(size_t)QK * DIM];
__device__ float g_WoutT [(size_t)DIM * HID];

__device__ __forceinline__ float silu(float x) { return x / (1.0f + expf(-x)); }
// round-to-nearest tf32 (removes HMMA truncation bias)
__device__ __forceinline__ float rtf(float f) {
    uint32_t u;
    asm("cvt.rna.tf32.f32 %0, %1;" : "=r"(u) : "f"(f));
    return __uint_as_float(u);
}

// ---------------- LayerNorm (UNCHANGED: clock canary) ----------------
__global__ void ln_kernel(const float* __restrict__ x,
                          const float* __restrict__ w,
                          const float* __restrict__ b) {
    int row = blockIdx.x;
    const float* xr = x + (size_t)row * DIM;
    float s = 0.f, s2 = 0.f;
    for (int i = threadIdx.x; i < DIM; i += blockDim.x) {
        float v = xr[i]; s += v; s2 += v * v;
    }
    __shared__ float sh[8], sh2[8];
    for (int o = 16; o > 0; o >>= 1) {
        s  += __shfl_down_sync(0xffffffffu, s, o);
        s2 += __shfl_down_sync(0xffffffffu, s2, o);
    }
    int wid = threadIdx.x >> 5, lane = threadIdx.x & 31;
    if (lane == 0) { sh[wid] = s; sh2[wid] = s2; }
    __syncthreads();
    if (threadIdx.x == 0) {
        float a = 0.f, a2 = 0.f;
        for (int i = 0; i < (int)(blockDim.x >> 5); i++) { a += sh[i]; a2 += sh2[i]; }
        sh[0] = a; sh2[0] = a2;
    }
    __syncthreads();
    float mu  = sh[0] * (1.0f / DIM);
    float var = sh2[0] * (1.0f / DIM) - mu * mu;
    float inv = rsqrtf(var + LN_EPS);
    float* o = g_normed + (size_t)row * DIM;
    for (int i = threadIdx.x; i < DIM; i += blockDim.x)
        o[i] = rtf((xr[i] - mu) * inv * w[i] + b[i]);
}

// ---------------- tiled transpose + tf32 rounding: in[R][C] -> out[C][R] ----------------
__global__ void transpose_k(const float* __restrict__ in, float* __restrict__ out,
                            int R, int C) {
    __shared__ float t[32][33];
    int c0 = blockIdx.x * 32, r0 = blockIdx.y * 32;
    int x = threadIdx.x, y = threadIdx.y;
#pragma unroll
    for (int j = 0; j < 32; j += 8)
        t[y + j][x] = in[(size_t)(r0 + y + j) * C + c0 + x];
    __syncthreads();
#pragma unroll
    for (int j = 0; j < 32; j += 8)
        out[(size_t)(c0 + y + j) * R + r0 + x] = rtf(t[x][y + j]);
}

// ---------------- exclusive group cumsum of lin_kv (tf32-rounded output) ----------------
__global__ void cumsum_kernel() {
    int p = blockIdx.x * blockDim.x + threadIdx.x;
    if (p >= NB * QK * HID) return;
    int b = p / (QK * HID);
    int off = p - b * (QK * HID);
    float acc = 0.f;
#pragma unroll
    for (int g = 0; g < NGPB; g++) {
        size_t idx = (size_t)(b * NGPB + g) * (QK * HID) + off;
        float t = g_linkv[idx];
        g_linkv[idx] = rtf(acc);
        acc += t;
    }
}

// ---------------- tf32 mma.sync GEMM, 128x128 CTA tile, K-chunk 32, 3-stage, LDSM ----------------
// CFG 1: A=g_normed, B=g_WhT (x<32) / g_WqkT (x==32), M=16384, K=1024
//        epilogue: n0<2048 -> silu->g_vT (transposed); n0<4096 -> silu->g_gate;
//                  n0>=4096 -> qk heads: qq(tf32)/lq/qkh(tf32) + lkT transposed
// CFG 7: A=g_qq[z], B=g_qkh[z], M=256,N=256,K=128; epi: /G + T5 bias + relu^2 + mask -> g_attn
// CFG 4: A=g_vT[z], B=g_lkT[z], M=2048,N=128,K=256; *(1/256) -> g_linkv [e][d]
// CFG 5 (merged): acc = attn[z]@vT[z] (K=256) + lq[z]@linkv[z] (K=128);
//        epi: g_ao = rtf(acc * gate)
// CFG 6: A=g_ao, B=g_WoutT, M=16384,N=1024,K=2048; +bout+x -> out
#define STG     18432                       // one 128x32 operand stage (stride 36 floats)
#define NSTAGE  3
#define GEMM_SMEM (NSTAGE * 2 * STG)        // 110592 (epilogue reuses first 68KB)

__device__ __forceinline__ uint32_t smem_u32(const void* p) {
    uint32_t a;
    asm("{ .reg .u64 t; cvta.to.shared.u64 t, %1; cvt.u32.u64 %0, t; }" : "=r"(a) : "l"(p));
    return a;
}
__device__ __forceinline__ void mma8(float* d, const uint32_t* a, const uint32_t* b) {
    asm volatile(
        "mma.sync.aligned.m16n8k8.row.col.f32.tf32.tf32.f32 "
        "{%0,%1,%2,%3}, {%4,%5,%6,%7}, {%8,%9}, {%0,%1,%2,%3};"
        : "+f"(d[0]), "+f"(d[1]), "+f"(d[2]), "+f"(d[3])
        : "r"(a[0]), "r"(a[1]), "r"(a[2]), "r"(a[3]), "r"(b[0]), "r"(b[1]));
}
__device__ __forceinline__ void ldsm4(uint32_t& r0, uint32_t& r1, uint32_t& r2, uint32_t& r3,
                                      uint32_t addr) {
    asm volatile("ldmatrix.sync.aligned.m8n8.x4.shared.b16 {%0,%1,%2,%3}, [%4];"
                 : "=r"(r0), "=r"(r1), "=r"(r2), "=r"(r3) : "r"(addr));
}

template <int CFG>
__global__ void __launch_bounds__(256)
gemm_tc(const float* __restrict__ pbias, const float* __restrict__ paux,
        float* __restrict__ pout,
        const float* __restrict__ pbias2, const float* __restrict__ pqkw,
        const float* __restrict__ pqkb) {
    constexpr int K  = (CFG == 1) ? 1024
                     : (CFG == 4) ? 256
                     : (CFG == 5 || CFG == 7) ? 128 : 2048;
    constexpr int NC = (CFG == 5) ? 12 : ((CFG == 1) ? 32 : K / 32);

    extern __shared__ char smem[];
    uint32_t sbase = smem_u32(smem);
    float* smf = (float*)smem;
    float* sb  = smf + 128 * 132;           // 256-entry T5 bias LUT (CFG7), free tail

    int tid = threadIdx.x, w = tid >> 5, lane = tid & 31;
    int grpL = lane >> 2, tig = lane & 3;
    int wm = w >> 2, wn = w & 3;            // 2 x 4 warp grid
    int z = blockIdx.z;
    int n0 = blockIdx.x * 128, m0 = blockIdx.y * 128;

    const float* Atile; const float* Btile;
    const float* A2tile = nullptr; const float* B2tile = nullptr;
    if (CFG == 1) {
        Atile = g_normed + (size_t)m0 * K;
        Btile = (n0 >= HV2) ? g_WqkT + (size_t)(n0 - HV2) * K
                            : g_WhT + (size_t)n0 * K;
    } else if (CFG == 7) {
        Atile = g_qq  + (size_t)z * G * QK + (size_t)m0 * QK;
        Btile = g_qkh + (size_t)z * G * QK + (size_t)n0 * QK;
    } else if (CFG == 4) {
        Atile = g_vT  + (size_t)z * HID * G + (size_t)m0 * G;
        Btile = g_lkT + (size_t)z * QK * G  + (size_t)n0 * G;
    } else if (CFG == 5) {
        Atile  = g_attn  + (size_t)z * G * G    + (size_t)m0 * G;    // K=256 phase
        Btile  = g_vT    + (size_t)z * HID * G  + (size_t)n0 * G;
        A2tile = g_lq    + (size_t)z * G * QK   + (size_t)m0 * QK;   // K=128 phase
        B2tile = g_linkv + (size_t)z * HID * QK + (size_t)n0 * QK;
    } else {
        Atile = g_ao    + (size_t)m0 * K;
        Btile = g_WoutT + (size_t)n0 * K;
    }

    float acc[4][4][4];
#pragma unroll
    for (int i = 0; i < 4; i++)
#pragma unroll
        for (int j = 0; j < 4; j++)
#pragma unroll
            for (int r = 0; r < 4; r++) acc[i][j][r] = 0.f;

    int ldr = tid >> 3, ldc = (tid & 7) * 4;          // global->smem mapping

    // ldmatrix lane-relative byte offsets
    int q = lane >> 3, rL = lane & 7;
    uint32_t laneA = (uint32_t)(((wm * 64 + (q & 1) * 8 + rL) * 36 + (q >> 1) * 4) * 4);
    uint32_t laneB = (uint32_t)(((wn * 32 + (q >> 1) * 8 + rL) * 36 + (q & 1) * 4) * 4) + STG;

    auto issue_chunk = [&](int cc, int st) {
        const float* Ap; const float* Bp; int ld;
        if (CFG == 5) {
            if (cc < 8) { Ap = Atile + cc * 32;        Bp = Btile + cc * 32;        ld = G;  }
            else        { Ap = A2tile + (cc - 8) * 32; Bp = B2tile + (cc - 8) * 32; ld = QK; }
        } else {
            Ap = Atile + cc * 32; Bp = Btile + cc * 32; ld = K;
        }
#pragma unroll
        for (int jj = 0; jj < 4; ++jj) {
            int r = ldr + jj * 32;
            uint32_t da = sbase + (uint32_t)(st * 2 * STG + (r * 36 + ldc) * 4);
            asm volatile("cp.async.cg.shared.global [%0], [%1], 16;"
                         :: "r"(da), "l"(Ap + (size_t)r * ld + ldc));
            asm volatile("cp.async.cg.shared.global [%0], [%1], 16;"
                         :: "r"(da + STG), "l"(Bp + (size_t)r * ld + ldc));
        }
    };

    // prologue: stages 0,1
    issue_chunk(0, 0);
    asm volatile("cp.async.commit_group;");
    issue_chunk(1, 1);
    asm volatile("cp.async.commit_group;");

    for (int c = 0; c < NC; ++c) {
        int pf = c + 2;
        if (pf < NC) issue_chunk(pf, pf % NSTAGE);
        asm volatile("cp.async.commit_group;");
        asm volatile("cp.async.wait_group 2;");
        __syncthreads();

        uint32_t abase = sbase + (uint32_t)((c % NSTAGE) * 2 * STG) + laneA;
        uint32_t bbase = sbase + (uint32_t)((c % NSTAGE) * 2 * STG) + laneB;
#pragma unroll
        for (int k8 = 0; k8 < 4; ++k8) {
            uint32_t af[4][4], bf[4][2];
#pragma unroll
            for (int i = 0; i < 4; ++i)
                ldsm4(af[i][0], af[i][1], af[i][2], af[i][3],
                      abase + (uint32_t)(i * 2304 + k8 * 32));
            ldsm4(bf[0][0], bf[0][1], bf[1][0], bf[1][1], bbase + (uint32_t)(k8 * 32));
            ldsm4(bf[2][0], bf[2][1], bf[3][0], bf[3][1],
                  bbase + (uint32_t)(2304 + k8 * 32));
#pragma unroll
            for (int i = 0; i < 4; ++i)
#pragma unroll
                for (int j = 0; j < 4; ++j)
                    mma8(acc[i][j], af[i], bf[j]);
        }
        __syncthreads();
    }

    // ---- stage accumulators into smem [128][132]; CFG7 also builds bias LUT ----
    if (CFG == 7) {
        int n = tid;
        int bucket;
        if (n <= 0)      bucket = 0;
        else if (n < 16) bucket = n;
        else {
            bucket = 16 + (int)(logf((float)n * (1.0f / 16.0f)) * 0.48089834696298783f * 16.0f);
            if (bucket > 31) bucket = 31;
        }
        sb[tid] = paux[bucket] * 11.313708498984761f;   // * sqrt(128)
    }
#pragma unroll
    for (int i = 0; i < 4; ++i) {
#pragma unroll
        for (int j = 0; j < 4; ++j) {
            int row = wm * 64 + i * 16 + grpL;
            int col = wn * 32 + j * 8 + tig * 2;
            smf[row * 132 + col]           = acc[i][j][0];
            smf[row * 132 + col + 1]       = acc[i][j][1];
            smf[(row + 8) * 132 + col]     = acc[i][j][2];
            smf[(row + 8) * 132 + col + 1] = acc[i][j][3];
        }
    }
    __syncthreads();

    // ---- epilogue / global write ----
    if (CFG == 1 && n0 < HID) {
        // v branch: write transposed into g_vT[grp][gn][t] (tf32: GEMM operand)
        int grp = m0 >> 8, tg0 = m0 & 255;
#pragma unroll
        for (int it = 0; it < 16; ++it) {
            int cc = it * 8 + w;
            int gn = n0 + cc;
            float bias = pbias[gn];
            int t = lane * 4;
            float4 o;
            o.x = rtf(silu(smf[(t + 0) * 132 + cc] + bias));
            o.y = rtf(silu(smf[(t + 1) * 132 + cc] + bias));
            o.z = rtf(silu(smf[(t + 2) * 132 + cc] + bias));
            o.w = rtf(silu(smf[(t + 3) * 132 + cc] + bias));
            *(float4*)&g_vT[((size_t)grp * HID + gn) * G + tg0 + t] = o;
        }
        return;
    }
    if (CFG == 1 && n0 >= HV2) {
        // qk heads: s = silu(acc + bqk); qq/qkh tf32 (CFG7 operands), lq tf32, lkT transposed
        int grp = m0 >> 8, tg0 = m0 & 255;
#pragma unroll
        for (int it = 0; it < 16; ++it) {
            int idx = tid + it * 256;
            int r = idx >> 5, c4 = (idx & 31) * 4;
            int tok = m0 + r;
            float4 bq = *(const float4*)&pbias2[c4];
            float4 s;
            s.x = silu(smf[r * 132 + c4 + 0] + bq.x);
            s.y = silu(smf[r * 132 + c4 + 1] + bq.y);
            s.z = silu(smf[r * 132 + c4 + 2] + bq.z);
            s.w = silu(smf[r * 132 + c4 + 3] + bq.w);
            smf[r * 132 + c4 + 0] = s.x; smf[r * 132 + c4 + 1] = s.y;
            smf[r * 132 + c4 + 2] = s.z; smf[r * 132 + c4 + 3] = s.w;
            float4 w0 = *(const float4*)&pqkw[c4];
            float4 b0 = *(const float4*)&pqkb[c4];
            float4 o0;
            o0.x = rtf(s.x * w0.x + b0.x); o0.y = rtf(s.y * w0.y + b0.y);
            o0.z = rtf(s.z * w0.z + b0.z); o0.w = rtf(s.w * w0.w + b0.w);
            *(float4*)&g_qq[(size_t)tok * QK + c4] = o0;
            float4 w1 = *(const float4*)&pqkw[QK + c4];
            float4 b1 = *(const float4*)&pqkb[QK + c4];
            float4 o1;
            o1.x = rtf(s.x * w1.x + b1.x); o1.y = rtf(s.y * w1.y + b1.y);
            o1.z = rtf(s.z * w1.z + b1.z); o1.w = rtf(s.w * w1.w + b1.w);
            *(float4*)&g_lq[(size_t)tok * QK + c4] = o1;
            float4 w2 = *(const float4*)&pqkw[2 * QK + c4];
            float4 b2 = *(const float4*)&pqkb[2 * QK + c4];
            float4 o2;
            o2.x = rtf(s.x * w2.x + b2.x); o2.y = rtf(s.y * w2.y + b2.y);
            o2.z = rtf(s.z * w2.z + b2.z); o2.w = rtf(s.w * w2.w + b2.w);
            *(float4*)&g_qkh[(size_t)tok * QK + c4] = o2;
        }
        __syncthreads();
#pragma unroll
        for (int it = 0; it < 16; ++it) {
            int cc = it * 8 + w;
            float w3 = pqkw[3 * QK + cc], b3 = pqkb[3 * QK + cc];
            int t = lane * 4;
            float4 o;
            o.x = rtf(smf[(t + 0) * 132 + cc] * w3 + b3);
            o.y = rtf(smf[(t + 1) * 132 + cc] * w3 + b3);
            o.z = rtf(smf[(t + 2) * 132 + cc] * w3 + b3);
            o.w = rtf(smf[(t + 3) * 132 + cc] * w3 + b3);
            *(float4*)&g_lkT[((size_t)grp * QK + cc) * G + tg0 + t] = o;
        }
        return;
    }
#pragma unroll
    for (int it = 0; it < 16; ++it) {
        int idx = tid + it * 256;              // 4096 float4 slots
        int r = idx >> 5, c4 = (idx & 31) * 4;
        int gm = m0 + r, gn = n0 + c4;
        float v0 = smf[r * 132 + c4 + 0];
        float v1 = smf[r * 132 + c4 + 1];
        float v2 = smf[r * 132 + c4 + 2];
        float v3 = smf[r * 132 + c4 + 3];
        if (CFG == 1) {                        // gate branch (2048 <= n0 < 4096)
            float4 o;
            o.x = silu(v0 + pbias[gn + 0]); o.y = silu(v1 + pbias[gn + 1]);
            o.z = silu(v2 + pbias[gn + 2]); o.w = silu(v3 + pbias[gn + 3]);
            *(float4*)&g_gate[(size_t)gm * HID + (gn - HID)] = o;
        } else if (CFG == 7) {                 // attention scores
            float o4[4] = {v0, v1, v2, v3};
            float4 o;
#pragma unroll
            for (int jj = 0; jj < 4; ++jj) {
                int d = gm - (gn + jj);
                float a = 0.f;
                if (d >= 0) {
                    float sim = o4[jj] * (1.0f / G) + sb[d];
                    a = sim > 0.f ? sim * sim : 0.f;
                }
                (&o.x)[jj] = rtf(a);
            }
            *(float4*)&g_attn[(size_t)z * (G * G) + (size_t)gm * G + gn] = o;
        } else if (CFG == 4) {                 // cumsum rounds later
            float4 o = make_float4(v0 * (1.0f / G), v1 * (1.0f / G),
                                   v2 * (1.0f / G), v3 * (1.0f / G));
            *(float4*)&g_linkv[((size_t)z * HID + gm) * QK + gn] = o;
        } else if (CFG == 5) {                 // merged quad+lin, gated
            size_t i0 = ((size_t)z * G + gm) * HID + gn;
            float4 gt = *(const float4*)&g_gate[i0];
            float4 o;
            o.x = rtf(v0 * gt.x); o.y = rtf(v1 * gt.y);
            o.z = rtf(v2 * gt.z); o.w = rtf(v3 * gt.w);
            *(float4*)&g_ao[i0] = o;
        } else {                               // CFG 6
            size_t i0 = (size_t)gm * DIM + gn;
            float4 xr = *(const float4*)&paux[i0];
            float4 o;
            o.x = v0 + pbias[gn + 0] + xr.x; o.y = v1 + pbias[gn + 1] + xr.y;
            o.z = v2 + pbias[gn + 2] + xr.z; o.w = v3 + pbias[gn + 3] + xr.w;
            *(float4*)&pout[i0] = o;
        }
    }
}

// ---------------- launch ----------------
extern "C" void kernel_launch(void* const* d_in, const int* in_sizes, int n_in,
                              void* d_out, int out_size) {
    const float* x    = (const float*)d_in[0];
    const float* ln_w = (const float*)d_in[1];
    const float* ln_b = (const float*)d_in[2];
    const float* Wh   = (const float*)d_in[3];
    const float* bh   = (const float*)d_in[4];
    const float* Wqk  = (const float*)d_in[5];
    const float* bqk  = (const float*)d_in[6];
    const float* qk_w = (const float*)d_in[7];
    const float* qk_b = (const float*)d_in[8];
    const float* rel  = (const float*)d_in[9];
    const float* Wout = (const float*)d_in[10];
    const float* bout = (const float*)d_in[11];
    float* out = (float*)d_out;

    cudaFuncSetAttribute(gemm_tc<1>, cudaFuncAttributeMaxDynamicSharedMemorySize, GEMM_SMEM);
    cudaFuncSetAttribute(gemm_tc<4>, cudaFuncAttributeMaxDynamicSharedMemorySize, GEMM_SMEM);
    cudaFuncSetAttribute(gemm_tc<5>, cudaFuncAttributeMaxDynamicSharedMemorySize, GEMM_SMEM);
    cudaFuncSetAttribute(gemm_tc<6>, cudaFuncAttributeMaxDynamicSharedMemorySize, GEMM_SMEM);
    cudaFuncSetAttribute(gemm_tc<7>, cudaFuncAttributeMaxDynamicSharedMemorySize, GEMM_SMEM);

    float* WhT;   cudaGetSymbolAddress((void**)&WhT,   g_WhT);
    float* WqkT;  cudaGetSymbolAddress((void**)&WqkT,  g_WqkT);
    float* WoutT; cudaGetSymbolAddress((void**)&WoutT, g_WoutT);

    // weight transposes (K-major B operands, tf32-rounded)
    transpose_k<<<dim3(HV2 / 32, DIM / 32), dim3(32, 8)>>>(Wh,   WhT,   DIM, HV2);
    transpose_k<<<dim3(QK  / 32, DIM / 32), dim3(32, 8)>>>(Wqk,  WqkT,  DIM, QK);
    transpose_k<<<dim3(DIM / 32, HID / 32), dim3(32, 8)>>>(Wout, WoutT, HID, DIM);

    // 1) LayerNorm
    ln_kernel<<<NTOK, 256>>>(x, ln_w, ln_b);

    // 2) fused: hv = silu(normed @ [Wh|Wqk] + [bh|bqk]) -> vT + gate + qk heads
    gemm_tc<1><<<dim3(HV2 / 128 + 1, NTOK / 128, 1), 256, GEMM_SMEM>>>(
        bh, nullptr, nullptr, bqk, qk_w, qk_b);

    // 3) attn scores (tensorized): relu^2(qq@qkh^T / G + T5 bias), causal
    gemm_tc<7><<<dim3(G / 128, G / 128, NGRP), 256, GEMM_SMEM>>>(
        nullptr, rel, nullptr, nullptr, nullptr, nullptr);

    // 4) lin_kv = v^T @ lin_k / g   -> [e][d]
    gemm_tc<4><<<dim3(1, HID / 128, NGRP), 256, GEMM_SMEM>>>(
        nullptr, nullptr, nullptr, nullptr, nullptr, nullptr);

    // 5) exclusive group cumsum
    cumsum_kernel<<<(NB * QK * HID) / 256, 256>>>();

    // 6) merged: ao = gate * (attn@v + lin_q@lin_kv)
    gemm_tc<5><<<dim3(HID / 128, G / 128, NGRP), 256, GEMM_SMEM>>>(
        nullptr, nullptr, nullptr, nullptr, nullptr, nullptr);

    // 7) out = ao @ Wout + bout + x
    gemm_tc<6><<<dim3(DIM / 128, NTOK / 128, 1), 256, GEMM_SMEM>>>(
        bout, x, out, nullptr, nullptr, nullptr);
}

// round 13
// speedup vs baseline: 1.2335x; 1.2335x over previous
#include <cuda_runtime.h>
#include <cuda_bf16.h>
#include <math.h>
#include <stdint.h>

// ---------------- problem constants ----------------
#define NTOK   16384        // 4 * 4096
#define DIM    1024
#define HID    2048
#define HV2    4096         // 2*HID
#define QK     128
#define G      256
#define NGRP   64           // 4 batches * 16 groups
#define NB     4
#define NGPB   16
#define LN_EPS 1e-5f

// ---------------- scratch (device globals) ----------------
__device__ __nv_bfloat16 g_normedB[(size_t)NTOK * DIM];   // bf16: CFG1 A
__device__ __nv_bfloat16 g_WhTB   [(size_t)HV2 * DIM];    // bf16: CFG1 B
__device__ __nv_bfloat16 g_WqkTB  [(size_t)QK * DIM];     // bf16: CFG1 B (heads block)
__device__ float g_WoutT [(size_t)DIM * HID];             // tf32: CFG6 B
__device__ float g_ao    [(size_t)NTOK * HID];            // tf32: CFG6 A
__device__ float g_vT    [(size_t)NGRP * HID * G];        // v transposed: [g][e][t] (tf32)
__device__ float g_gate  [(size_t)NTOK * HID];
__device__ float g_qq    [(size_t)NTOK * QK];             // (tf32)
__device__ float g_lq    [(size_t)NTOK * QK];
__device__ float g_qkh   [(size_t)NTOK * QK];             // (tf32)
__device__ float g_lkT   [(size_t)NGRP * QK * G];         // lin_k transposed (tf32)
__device__ float g_attn  [(size_t)NGRP * G * G];
__device__ float g_linkv [(size_t)NGRP * HID * QK];       // [g][e][d]

__device__ __forceinline__ float silu(float x) { return x / (1.0f + expf(-x)); }
// round-to-nearest tf32 (removes HMMA truncation bias)
__device__ __forceinline__ float rtf(float f) {
    uint32_t u;
    asm("cvt.rna.tf32.f32 %0, %1;" : "=r"(u) : "f"(f));
    return __uint_as_float(u);
}

// ---------------- LayerNorm (bf16 output: CFG1 operand) ----------------
__global__ void ln_kernel(const float* __restrict__ x,
                          const float* __restrict__ w,
                          const float* __restrict__ b) {
    int row = blockIdx.x;
    const float* xr = x + (size_t)row * DIM;
    float s = 0.f, s2 = 0.f;
    for (int i = threadIdx.x; i < DIM; i += blockDim.x) {
        float v = xr[i]; s += v; s2 += v * v;
    }
    __shared__ float sh[8], sh2[8];
    for (int o = 16; o > 0; o >>= 1) {
        s  += __shfl_down_sync(0xffffffffu, s, o);
        s2 += __shfl_down_sync(0xffffffffu, s2, o);
    }
    int wid = threadIdx.x >> 5, lane = threadIdx.x & 31;
    if (lane == 0) { sh[wid] = s; sh2[wid] = s2; }
    __syncthreads();
    if (threadIdx.x == 0) {
        float a = 0.f, a2 = 0.f;
        for (int i = 0; i < (int)(blockDim.x >> 5); i++) { a += sh[i]; a2 += sh2[i]; }
        sh[0] = a; sh2[0] = a2;
    }
    __syncthreads();
    float mu  = sh[0] * (1.0f / DIM);
    float var = sh2[0] * (1.0f / DIM) - mu * mu;
    float inv = rsqrtf(var + LN_EPS);
    __nv_bfloat16* o = g_normedB + (size_t)row * DIM;
    for (int i = threadIdx.x; i < DIM; i += blockDim.x)
        o[i] = __float2bfloat16((xr[i] - mu) * inv * w[i] + b[i]);
}

// ---------------- tiled transposes: -> bf16 and -> tf32 ----------------
__global__ void transpose_b(const float* __restrict__ in, __nv_bfloat16* __restrict__ out,
                            int R, int C) {
    __shared__ float t[32][33];
    int c0 = blockIdx.x * 32, r0 = blockIdx.y * 32;
    int x = threadIdx.x, y = threadIdx.y;
#pragma unroll
    for (int j = 0; j < 32; j += 8)
        t[y + j][x] = in[(size_t)(r0 + y + j) * C + c0 + x];
    __syncthreads();
#pragma unroll
    for (int j = 0; j < 32; j += 8)
        out[(size_t)(c0 + y + j) * R + r0 + x] = __float2bfloat16(t[x][y + j]);
}
__global__ void transpose_f(const float* __restrict__ in, float* __restrict__ out,
                            int R, int C) {
    __shared__ float t[32][33];
    int c0 = blockIdx.x * 32, r0 = blockIdx.y * 32;
    int x = threadIdx.x, y = threadIdx.y;
#pragma unroll
    for (int j = 0; j < 32; j += 8)
        t[y + j][x] = in[(size_t)(r0 + y + j) * C + c0 + x];
    __syncthreads();
#pragma unroll
    for (int j = 0; j < 32; j += 8)
        out[(size_t)(c0 + y + j) * R + r0 + x] = rtf(t[x][y + j]);
}

// ---------------- exclusive group cumsum of lin_kv (UNCHANGED: clock canary) ----------------
__global__ void cumsum_kernel() {
    int p = blockIdx.x * blockDim.x + threadIdx.x;
    if (p >= NB * QK * HID) return;
    int b = p / (QK * HID);
    int off = p - b * (QK * HID);
    float acc = 0.f;
#pragma unroll
    for (int g = 0; g < NGPB; g++) {
        size_t idx = (size_t)(b * NGPB + g) * (QK * HID) + off;
        float t = g_linkv[idx];
        g_linkv[idx] = rtf(acc);
        acc += t;
    }
}

// ---------------- mma.sync GEMM, 128x128 CTA tile, K-chunk 32, 2-stage, LDSM ----------------
// CFG 1 (bf16): A=g_normedB, B=g_WhTB (x<32) / g_WqkTB (x==32), M=16384, K=1024
//        epilogue: n0<2048 -> silu->g_vT; n0<4096 -> silu->g_gate; n0>=4096 -> qk heads
// CFG 7 (tf32): qq@qkh^T; /G + T5 bias + relu^2 + mask -> g_attn
// CFG 4 (tf32): vT@lkT / 256 -> g_linkv
// CFG 5 (tf32, merged): attn@vT (K=256) + lq@linkv (K=128); g_ao = rtf(acc*gate)
// CFG 6 (tf32): g_ao @ g_WoutT, K=2048; +bout+x -> out
#define STG     18432                       // tf32 operand stage (128x36 floats)
#define STGB    10240                       // bf16 operand stage (128x40 bf16)
#define GEMM_SMEM (4 * STG)                 // 73728 (epilogue reuses first 68KB)

__device__ __forceinline__ uint32_t smem_u32(const void* p) {
    uint32_t a;
    asm("{ .reg .u64 t; cvta.to.shared.u64 t, %1; cvt.u32.u64 %0, t; }" : "=r"(a) : "l"(p));
    return a;
}
__device__ __forceinline__ void mma8(float* d, const uint32_t* a, const uint32_t* b) {
    asm volatile(
        "mma.sync.aligned.m16n8k8.row.col.f32.tf32.tf32.f32 "
        "{%0,%1,%2,%3}, {%4,%5,%6,%7}, {%8,%9}, {%0,%1,%2,%3};"
        : "+f"(d[0]), "+f"(d[1]), "+f"(d[2]), "+f"(d[3])
        : "r"(a[0]), "r"(a[1]), "r"(a[2]), "r"(a[3]), "r"(b[0]), "r"(b[1]));
}
__device__ __forceinline__ void mma16(float* d, const uint32_t* a, const uint32_t* b) {
    asm volatile(
        "mma.sync.aligned.m16n8k16.row.col.f32.bf16.bf16.f32 "
        "{%0,%1,%2,%3}, {%4,%5,%6,%7}, {%8,%9}, {%0,%1,%2,%3};"
        : "+f"(d[0]), "+f"(d[1]), "+f"(d[2]), "+f"(d[3])
        : "r"(a[0]), "r"(a[1]), "r"(a[2]), "r"(a[3]), "r"(b[0]), "r"(b[1]));
}
__device__ __forceinline__ void ldsm4(uint32_t& r0, uint32_t& r1, uint32_t& r2, uint32_t& r3,
                                      uint32_t addr) {
    asm volatile("ldmatrix.sync.aligned.m8n8.x4.shared.b16 {%0,%1,%2,%3}, [%4];"
                 : "=r"(r0), "=r"(r1), "=r"(r2), "=r"(r3) : "r"(addr));
}

template <int CFG>
__global__ void __launch_bounds__(256)
gemm_tc(const float* __restrict__ pbias, const float* __restrict__ paux,
        float* __restrict__ pout,
        const float* __restrict__ pbias2, const float* __restrict__ pqkw,
        const float* __restrict__ pqkb) {
    constexpr bool BF16 = (CFG == 1);
    constexpr int K  = (CFG == 1) ? 1024
                     : (CFG == 4) ? 256
                     : (CFG == 5 || CFG == 7) ? 128 : 2048;
    constexpr int NC = (CFG == 5) ? 12 : K / 32;

    extern __shared__ char smem[];
    uint32_t sbase = smem_u32(smem);
    float* smf = (float*)smem;
    float* sb  = smf + 128 * 132;           // 256-entry T5 bias LUT (CFG7), free tail

    int tid = threadIdx.x, w = tid >> 5, lane = tid & 31;
    int grpL = lane >> 2, tig = lane & 3;
    int wm = w >> 2, wn = w & 3;            // 2 x 4 warp grid
    int z = blockIdx.z;
    int n0 = blockIdx.x * 128, m0 = blockIdx.y * 128;
    int q = lane >> 3, rL = lane & 7;

    float acc[4][4][4];
#pragma unroll
    for (int i = 0; i < 4; i++)
#pragma unroll
        for (int j = 0; j < 4; j++)
#pragma unroll
            for (int r = 0; r < 4; r++) acc[i][j][r] = 0.f;

    if constexpr (BF16) {
        // ---------- bf16 mainloop: m16n8k16, tile 128x32 bf16, stride 40 elems ----------
        const __nv_bfloat16* At = g_normedB + (size_t)m0 * K;
        const __nv_bfloat16* Bt = (n0 >= HV2) ? g_WqkTB + (size_t)(n0 - HV2) * K
                                              : g_WhTB + (size_t)n0 * K;
        int ldrb = tid >> 2, ldcb = (tid & 3) * 8;
        uint32_t laneA = (uint32_t)(((wm * 64 + (q & 1) * 8 + rL) * 40 + (q >> 1) * 8) * 2);
        uint32_t laneB = (uint32_t)(((wn * 32 + (q >> 1) * 8 + rL) * 40 + (q & 1) * 8) * 2) + STGB;

#define ISSUE_B(cc, st)                                                              \
        {                                                                            \
            _Pragma("unroll")                                                        \
            for (int jj = 0; jj < 2; ++jj) {                                         \
                int r = ldrb + jj * 64;                                              \
                uint32_t da = sbase + (uint32_t)((st) * 2 * STGB + (r * 40 + ldcb) * 2); \
                asm volatile("cp.async.cg.shared.global [%0], [%1], 16;"             \
                             :: "r"(da), "l"(At + (size_t)r * K + (cc) * 32 + ldcb)); \
                asm volatile("cp.async.cg.shared.global [%0], [%1], 16;"             \
                             :: "r"(da + STGB), "l"(Bt + (size_t)r * K + (cc) * 32 + ldcb)); \
            }                                                                        \
        }
        ISSUE_B(0, 0);
        asm volatile("cp.async.commit_group;");
        for (int c = 0; c < NC; ++c) {
            if (c + 1 < NC) {
                ISSUE_B(c + 1, (c + 1) & 1);
                asm volatile("cp.async.commit_group;");
                asm volatile("cp.async.wait_group 1;");
            } else {
                asm volatile("cp.async.wait_group 0;");
            }
            __syncthreads();
            uint32_t abase = sbase + (uint32_t)((c & 1) * 2 * STGB) + laneA;
            uint32_t bbase = sbase + (uint32_t)((c & 1) * 2 * STGB) + laneB;
#pragma unroll
            for (int s = 0; s < 2; ++s) {
                uint32_t af[4][4], bff[4][2];
#pragma unroll
                for (int i = 0; i < 4; ++i)
                    ldsm4(af[i][0], af[i][1], af[i][2], af[i][3],
                          abase + (uint32_t)(i * 1280 + s * 32));
                ldsm4(bff[0][0], bff[0][1], bff[1][0], bff[1][1],
                      bbase + (uint32_t)(s * 32));
                ldsm4(bff[2][0], bff[2][1], bff[3][0], bff[3][1],
                      bbase + (uint32_t)(1280 + s * 32));
#pragma unroll
                for (int i = 0; i < 4; ++i)
#pragma unroll
                    for (int j = 0; j < 4; ++j)
                        mma16(acc[i][j], af[i], bff[j]);
            }
            __syncthreads();
        }
#undef ISSUE_B
    } else {
        // ---------- tf32 mainloop: m16n8k8, tile 128x32 fp32, stride 36 floats ----------
        const float* Atile; const float* Btile;
        const float* A2tile = nullptr; const float* B2tile = nullptr;
        if constexpr (CFG == 7) {
            Atile = g_qq  + (size_t)z * G * QK + (size_t)m0 * QK;
            Btile = g_qkh + (size_t)z * G * QK + (size_t)n0 * QK;
        } else if constexpr (CFG == 4) {
            Atile = g_vT  + (size_t)z * HID * G + (size_t)m0 * G;
            Btile = g_lkT + (size_t)z * QK * G  + (size_t)n0 * G;
        } else if constexpr (CFG == 5) {
            Atile  = g_attn  + (size_t)z * G * G    + (size_t)m0 * G;
            Btile  = g_vT    + (size_t)z * HID * G  + (size_t)n0 * G;
            A2tile = g_lq    + (size_t)z * G * QK   + (size_t)m0 * QK;
            B2tile = g_linkv + (size_t)z * HID * QK + (size_t)n0 * QK;
        } else {
            Atile = g_ao    + (size_t)m0 * K;
            Btile = g_WoutT + (size_t)n0 * K;
        }
        int ldr = tid >> 3, ldc = (tid & 7) * 4;
        uint32_t laneA = (uint32_t)(((wm * 64 + (q & 1) * 8 + rL) * 36 + (q >> 1) * 4) * 4);
        uint32_t laneB = (uint32_t)(((wn * 32 + (q >> 1) * 8 + rL) * 36 + (q & 1) * 4) * 4) + STG;

        auto issue_chunk = [&](int cc, int st) {
            const float* Ap; const float* Bp; int ld;
            if (CFG == 5 && cc >= 8) { Ap = A2tile + (cc - 8) * 32; Bp = B2tile + (cc - 8) * 32; ld = QK; }
            else if (CFG == 5)       { Ap = Atile + cc * 32;        Bp = Btile + cc * 32;        ld = G;  }
            else                     { Ap = Atile + cc * 32;        Bp = Btile + cc * 32;        ld = K;  }
#pragma unroll
            for (int jj = 0; jj < 4; ++jj) {
                int r = ldr + jj * 32;
                uint32_t da = sbase + (uint32_t)(st * 2 * STG + (r * 36 + ldc) * 4);
                asm volatile("cp.async.cg.shared.global [%0], [%1], 16;"
                             :: "r"(da), "l"(Ap + (size_t)r * ld + ldc));
                asm volatile("cp.async.cg.shared.global [%0], [%1], 16;"
                             :: "r"(da + STG), "l"(Bp + (size_t)r * ld + ldc));
            }
        };
        issue_chunk(0, 0);
        asm volatile("cp.async.commit_group;");
        for (int c = 0; c < NC; ++c) {
            if (c + 1 < NC) {
                issue_chunk(c + 1, (c + 1) & 1);
                asm volatile("cp.async.commit_group;");
                asm volatile("cp.async.wait_group 1;");
            } else {
                asm volatile("cp.async.wait_group 0;");
            }
            __syncthreads();
            uint32_t abase = sbase + (uint32_t)((c & 1) * 2 * STG) + laneA;
            uint32_t bbase = sbase + (uint32_t)((c & 1) * 2 * STG) + laneB;
#pragma unroll
            for (int k8 = 0; k8 < 4; ++k8) {
                uint32_t af[4][4], bff[4][2];
#pragma unroll
                for (int i = 0; i < 4; ++i)
                    ldsm4(af[i][0], af[i][1], af[i][2], af[i][3],
                          abase + (uint32_t)(i * 2304 + k8 * 32));
                ldsm4(bff[0][0], bff[0][1], bff[1][0], bff[1][1], bbase + (uint32_t)(k8 * 32));
                ldsm4(bff[2][0], bff[2][1], bff[3][0], bff[3][1],
                      bbase + (uint32_t)(2304 + k8 * 32));
#pragma unroll
                for (int i = 0; i < 4; ++i)
#pragma unroll
                    for (int j = 0; j < 4; ++j)
                        mma8(acc[i][j], af[i], bff[j]);
            }
            __syncthreads();
        }
    }

    // ---- stage accumulators into smem [128][132]; CFG7 also builds bias LUT ----
    if (CFG == 7) {
        int n = tid;
        int bucket;
        if (n <= 0)      bucket = 0;
        else if (n < 16) bucket = n;
        else {
            bucket = 16 + (int)(logf((float)n * (1.0f / 16.0f)) * 0.48089834696298783f * 16.0f);
            if (bucket > 31) bucket = 31;
        }
        sb[tid] = paux[bucket] * 11.313708498984761f;   // * sqrt(128)
    }
#pragma unroll
    for (int i = 0; i < 4; ++i) {
#pragma unroll
        for (int j = 0; j < 4; ++j) {
            int row = wm * 64 + i * 16 + grpL;
            int col = wn * 32 + j * 8 + tig * 2;
            smf[row * 132 + col]           = acc[i][j][0];
            smf[row * 132 + col + 1]       = acc[i][j][1];
            smf[(row + 8) * 132 + col]     = acc[i][j][2];
            smf[(row + 8) * 132 + col + 1] = acc[i][j][3];
        }
    }
    __syncthreads();

    // ---- epilogue / global write ----
    if (CFG == 1 && n0 < HID) {
        // v branch: write transposed into g_vT[grp][gn][t] (tf32: CFG4/5 operand)
        int grp = m0 >> 8, tg0 = m0 & 255;
#pragma unroll
        for (int it = 0; it < 16; ++it) {
            int cc = it * 8 + w;
            int gn = n0 + cc;
            float bias = pbias[gn];
            int t = lane * 4;
            float4 o;
            o.x = rtf(silu(smf[(t + 0) * 132 + cc] + bias));
            o.y = rtf(silu(smf[(t + 1) * 132 + cc] + bias));
            o.z = rtf(silu(smf[(t + 2) * 132 + cc] + bias));
            o.w = rtf(silu(smf[(t + 3) * 132 + cc] + bias));
            *(float4*)&g_vT[((size_t)grp * HID + gn) * G + tg0 + t] = o;
        }
        return;
    }
    if (CFG == 1 && n0 >= HV2) {
        // qk heads: s = silu(acc + bqk); qq/qkh/lq tf32, lkT transposed
        int grp = m0 >> 8, tg0 = m0 & 255;
#pragma unroll
        for (int it = 0; it < 16; ++it) {
            int idx = tid + it * 256;
            int r = idx >> 5, c4 = (idx & 31) * 4;
            int tok = m0 + r;
            float4 bq = *(const float4*)&pbias2[c4];
            float4 s;
            s.x = silu(smf[r * 132 + c4 + 0] + bq.x);
            s.y = silu(smf[r * 132 + c4 + 1] + bq.y);
            s.z = silu(smf[r * 132 + c4 + 2] + bq.z);
            s.w = silu(smf[r * 132 + c4 + 3] + bq.w);
            smf[r * 132 + c4 + 0] = s.x; smf[r * 132 + c4 + 1] = s.y;
            smf[r * 132 + c4 + 2] = s.z; smf[r * 132 + c4 + 3] = s.w;
            float4 w0 = *(const float4*)&pqkw[c4];
            float4 b0 = *(const float4*)&pqkb[c4];
            float4 o0;
            o0.x = rtf(s.x * w0.x + b0.x); o0.y = rtf(s.y * w0.y + b0.y);
            o0.z = rtf(s.z * w0.z + b0.z); o0.w = rtf(s.w * w0.w + b0.w);
            *(float4*)&g_qq[(size_t)tok * QK + c4] = o0;
            float4 w1 = *(const float4*)&pqkw[QK + c4];
            float4 b1 = *(const float4*)&pqkb[QK + c4];
            float4 o1;
            o1.x = rtf(s.x * w1.x + b1.x); o1.y = rtf(s.y * w1.y + b1.y);
            o1.z = rtf(s.z * w1.z + b1.z); o1.w = rtf(s.w * w1.w + b1.w);
            *(float4*)&g_lq[(size_t)tok * QK + c4] = o1;
            float4 w2 = *(const float4*)&pqkw[2 * QK + c4];
            float4 b2 = *(const float4*)&pqkb[2 * QK + c4];
            float4 o2;
            o2.x = rtf(s.x * w2.x + b2.x); o2.y = rtf(s.y * w2.y + b2.y);
            o2.z = rtf(s.z * w2.z + b2.z); o2.w = rtf(s.w * w2.w + b2.w);
            *(float4*)&g_qkh[(size_t)tok * QK + c4] = o2;
        }
        __syncthreads();
#pragma unroll
        for (int it = 0; it < 16; ++it) {
            int cc = it * 8 + w;
            float w3 = pqkw[3 * QK + cc], b3 = pqkb[3 * QK + cc];
            int t = lane * 4;
            float4 o;
            o.x = rtf(smf[(t + 0) * 132 + cc] * w3 + b3);
            o.y = rtf(smf[(t + 1) * 132 + cc] * w3 + b3);
            o.z = rtf(smf[(t + 2) * 132 + cc] * w3 + b3);
            o.w = rtf(smf[(t + 3) * 132 + cc] * w3 + b3);
            *(float4*)&g_lkT[((size_t)grp * QK + cc) * G + tg0 + t] = o;
        }
        return;
    }
#pragma unroll
    for (int it = 0; it < 16; ++it) {
        int idx = tid + it * 256;              // 4096 float4 slots
        int r = idx >> 5, c4 = (idx & 31) * 4;
        int gm = m0 + r, gn = n0 + c4;
        float v0 = smf[r * 132 + c4 + 0];
        float v1 = smf[r * 132 + c4 + 1];
        float v2 = smf[r * 132 + c4 + 2];
        float v3 = smf[r * 132 + c4 + 3];
        if (CFG == 1) {                        // gate branch (2048 <= n0 < 4096)
            float4 o;
            o.x = silu(v0 + pbias[gn + 0]); o.y = silu(v1 + pbias[gn + 1]);
            o.z = silu(v2 + pbias[gn + 2]); o.w = silu(v3 + pbias[gn + 3]);
            *(float4*)&g_gate[(size_t)gm * HID + (gn - HID)] = o;
        } else if (CFG == 7) {                 // attention scores
            float o4[4] = {v0, v1, v2, v3};
            float4 o;
#pragma unroll
            for (int jj = 0; jj < 4; ++jj) {
                int d = gm - (gn + jj);
                float a = 0.f;
                if (d >= 0) {
                    float sim = o4[jj] * (1.0f / G) + sb[d];
                    a = sim > 0.f ? sim * sim : 0.f;
                }
                (&o.x)[jj] = rtf(a);
            }
            *(float4*)&g_attn[(size_t)z * (G * G) + (size_t)gm * G + gn] = o;
        } else if (CFG == 4) {                 // cumsum rounds later
            float4 o = make_float4(v0 * (1.0f / G), v1 * (1.0f / G),
                                   v2 * (1.0f / G), v3 * (1.0f / G));
            *(float4*)&g_linkv[((size_t)z * HID + gm) * QK + gn] = o;
        } else if (CFG == 5) {                 // merged quad+lin, gated -> tf32 (CFG6 A)
            size_t i0 = ((size_t)z * G + gm) * HID + gn;
            float4 gt = *(const float4*)&g_gate[i0];
            float4 o;
            o.x = rtf(v0 * gt.x); o.y = rtf(v1 * gt.y);
            o.z = rtf(v2 * gt.z); o.w = rtf(v3 * gt.w);
            *(float4*)&g_ao[i0] = o;
        } else {                               // CFG 6
            size_t i0 = (size_t)gm * DIM + gn;
            float4 xr = *(const float4*)&paux[i0];
            float4 o;
            o.x = v0 + pbias[gn + 0] + xr.x; o.y = v1 + pbias[gn + 1] + xr.y;
            o.z = v2 + pbias[gn + 2] + xr.z; o.w = v3 + pbias[gn + 3] + xr.w;
            *(float4*)&pout[i0] = o;
        }
    }
}

// ---------------- launch ----------------
extern "C" void kernel_launch(void* const* d_in, const int* in_sizes, int n_in,
                              void* d_out, int out_size) {
    const float* x    = (const float*)d_in[0];
    const float* ln_w = (const float*)d_in[1];
    const float* ln_b = (const float*)d_in[2];
    const float* Wh   = (const float*)d_in[3];
    const float* bh   = (const float*)d_in[4];
    const float* Wqk  = (const float*)d_in[5];
    const float* bqk  = (const float*)d_in[6];
    const float* qk_w = (const float*)d_in[7];
    const float* qk_b = (const float*)d_in[8];
    const float* rel  = (const float*)d_in[9];
    const float* Wout = (const float*)d_in[10];
    const float* bout = (const float*)d_in[11];
    float* out = (float*)d_out;

    cudaFuncSetAttribute(gemm_tc<1>, cudaFuncAttributeMaxDynamicSharedMemorySize, GEMM_SMEM);
    cudaFuncSetAttribute(gemm_tc<4>, cudaFuncAttributeMaxDynamicSharedMemorySize, GEMM_SMEM);
    cudaFuncSetAttribute(gemm_tc<5>, cudaFuncAttributeMaxDynamicSharedMemorySize, GEMM_SMEM);
    cudaFuncSetAttribute(gemm_tc<6>, cudaFuncAttributeMaxDynamicSharedMemorySize, GEMM_SMEM);
    cudaFuncSetAttribute(gemm_tc<7>, cudaFuncAttributeMaxDynamicSharedMemorySize, GEMM_SMEM);

    __nv_bfloat16* WhT;   cudaGetSymbolAddress((void**)&WhT,   g_WhTB);
    __nv_bfloat16* WqkT;  cudaGetSymbolAddress((void**)&WqkT,  g_WqkTB);
    float* WoutT;         cudaGetSymbolAddress((void**)&WoutT, g_WoutT);

    // weight transposes: Wh/Wqk -> bf16 K-major, Wout -> tf32 K-major
    transpose_b<<<dim3(HV2 / 32, DIM / 32), dim3(32, 8)>>>(Wh,   WhT,   DIM, HV2);
    transpose_b<<<dim3(QK  / 32, DIM / 32), dim3(32, 8)>>>(Wqk,  WqkT,  DIM, QK);
    transpose_f<<<dim3(DIM / 32, HID / 32), dim3(32, 8)>>>(Wout, WoutT, HID, DIM);

    // 1) LayerNorm -> bf16
    ln_kernel<<<NTOK, 256>>>(x, ln_w, ln_b);

    // 2) fused bf16 GEMM: hv = silu(normed @ [Wh|Wqk] + [bh|bqk]) -> vT + gate + qk heads
    gemm_tc<1><<<dim3(HV2 / 128 + 1, NTOK / 128, 1), 256, GEMM_SMEM>>>(
        bh, nullptr, nullptr, bqk, qk_w, qk_b);

    // 3) attn scores (tf32): relu^2(qq@qkh^T / G + T5 bias), causal
    gemm_tc<7><<<dim3(G / 128, G / 128, NGRP), 256, GEMM_SMEM>>>(
        nullptr, rel, nullptr, nullptr, nullptr, nullptr);

    // 4) lin_kv = v^T @ lin_k / g
    gemm_tc<4><<<dim3(1, HID / 128, NGRP), 256, GEMM_SMEM>>>(
        nullptr, nullptr, nullptr, nullptr, nullptr, nullptr);

    // 5) exclusive group cumsum
    cumsum_kernel<<<(NB * QK * HID) / 256, 256>>>();

    // 6) merged (tf32): ao = gate * (attn@v + lin_q@lin_kv) -> tf32
    gemm_tc<5><<<dim3(HID / 128, G / 128, NGRP), 256, GEMM_SMEM>>>(
        nullptr, nullptr, nullptr, nullptr, nullptr, nullptr);

    // 7) tf32 GEMM: out = ao @ Wout + bout + x
    gemm_tc<6><<<dim3(DIM / 128, NTOK / 128, 1), 256, GEMM_SMEM>>>(
        bout, x, out, nullptr, nullptr, nullptr);
}

// round 16
// speedup vs baseline: 1.5615x; 1.2659x over previous
#include <cuda_runtime.h>
#include <cuda_fp16.h>
#include <math.h>
#include <stdint.h>

// ---------------- problem constants ----------------
#define NTOK   16384        // 4 * 4096
#define DIM    1024
#define HID    2048
#define HV2    4096         // 2*HID
#define QK     128
#define G      256
#define NGRP   64           // 4 batches * 16 groups
#define NB     4
#define NGPB   16
#define LN_EPS 1e-5f

// ---------------- scratch (device globals; all GEMM operands fp16) ----------------
__device__ __half g_normedH[(size_t)NTOK * DIM];
__device__ __half g_WhTH   [(size_t)HV2 * DIM];
__device__ __half g_WqkTH  [(size_t)QK * DIM];
__device__ __half g_WoutTH [(size_t)DIM * HID];
__device__ __half g_aoH    [(size_t)NTOK * HID];
__device__ __half g_vTH    [(size_t)NGRP * HID * G];   // v transposed: [g][e][t]
__device__ __half g_qqH    [(size_t)NTOK * QK];
__device__ __half g_lqH    [(size_t)NTOK * QK];
__device__ __half g_qkhH   [(size_t)NTOK * QK];
__device__ __half g_lkTH   [(size_t)NGRP * QK * G];    // lin_k transposed: [g][d][t]
__device__ __half g_attnH  [(size_t)NGRP * G * G];
__device__ __half g_linkvH [(size_t)NGRP * HID * QK];  // [g][e][d]
__device__ float  g_gate   [(size_t)NTOK * HID];       // fp32 (epilogue-only consumer)

__device__ __forceinline__ float silu(float x) { return x / (1.0f + expf(-x)); }
__device__ __forceinline__ uint32_t pack2h(float a, float b) {
    __half2 h = __floats2half2_rn(a, b);
    return *(uint32_t*)&h;
}

// ---------------- LayerNorm (fp16 output: CFG1 operand) ----------------
__global__ void ln_kernel(const float* __restrict__ x,
                          const float* __restrict__ w,
                          const float* __restrict__ b) {
    int row = blockIdx.x;
    const float* xr = x + (size_t)row * DIM;
    float s = 0.f, s2 = 0.f;
    for (int i = threadIdx.x; i < DIM; i += blockDim.x) {
        float v = xr[i]; s += v; s2 += v * v;
    }
    __shared__ float sh[8], sh2[8];
    for (int o = 16; o > 0; o >>= 1) {
        s  += __shfl_down_sync(0xffffffffu, s, o);
        s2 += __shfl_down_sync(0xffffffffu, s2, o);
    }
    int wid = threadIdx.x >> 5, lane = threadIdx.x & 31;
    if (lane == 0) { sh[wid] = s; sh2[wid] = s2; }
    __syncthreads();
    if (threadIdx.x == 0) {
        float a = 0.f, a2 = 0.f;
        for (int i = 0; i < (int)(blockDim.x >> 5); i++) { a += sh[i]; a2 += sh2[i]; }
        sh[0] = a; sh2[0] = a2;
    }
    __syncthreads();
    float mu  = sh[0] * (1.0f / DIM);
    float var = sh2[0] * (1.0f / DIM) - mu * mu;
    float inv = rsqrtf(var + LN_EPS);
    __half* o = g_normedH + (size_t)row * DIM;
    for (int i = threadIdx.x; i < DIM; i += blockDim.x)
        o[i] = __float2half_rn((xr[i] - mu) * inv * w[i] + b[i]);
}

// ---------------- tiled transpose -> fp16: in[R][C] -> out[C][R] ----------------
__global__ void transpose_h(const float* __restrict__ in, __half* __restrict__ out,
                            int R, int C) {
    __shared__ float t[32][33];
    int c0 = blockIdx.x * 32, r0 = blockIdx.y * 32;
    int x = threadIdx.x, y = threadIdx.y;
#pragma unroll
    for (int j = 0; j < 32; j += 8)
        t[y + j][x] = in[(size_t)(r0 + y + j) * C + c0 + x];
    __syncthreads();
#pragma unroll
    for (int j = 0; j < 32; j += 8)
        out[(size_t)(c0 + y + j) * R + r0 + x] = __float2half_rn(t[x][y + j]);
}

// ---------------- exclusive group cumsum of lin_kv (fp32 accumulate, fp16 store) ----------------
__global__ void cumsum_kernel() {
    int p = blockIdx.x * blockDim.x + threadIdx.x;
    if (p >= NB * QK * HID) return;
    int b = p / (QK * HID);
    int off = p - b * (QK * HID);
    float acc = 0.f;
#pragma unroll
    for (int g = 0; g < NGPB; g++) {
        size_t idx = (size_t)(b * NGPB + g) * (QK * HID) + off;
        float t = __half2float(g_linkvH[idx]);
        g_linkvH[idx] = __float2half_rn(acc);
        acc += t;
    }
}

// ---------------- fp16 mma.sync GEMM, 128x128 CTA tile, K-chunk 32, 2-stage, LDSM ----------------
// All operands K-major fp16; accumulate fp32 (m16n8k16.f32.f16.f16.f32).
// CFG 1: A=g_normedH, B=g_WhTH (x<32) / g_WqkTH (x==32), M=16384, K=1024
//        epilogue: n0<2048 -> silu->vTH; n0<4096 -> silu->g_gate; n0>=4096 -> qk heads
// CFG 7: qq@qkh^T; /G + T5 bias + relu^2 + mask -> attnH
// CFG 4: vT@lkT / 256 -> linkvH
// CFG 5 (merged): attn@vT (K=256) + lq@linkv (K=128); aoH = fp16(acc*gate)
// CFG 6: aoH @ WoutTH, K=2048; +bout+x -> out (fp32)
#define STGB    10240                       // fp16 operand stage (128x40 halves)
#define GEMM_SMEM 69632                     // epilogue smf[128][132] f32 + 1KB LUT

__device__ __forceinline__ uint32_t smem_u32(const void* p) {
    uint32_t a;
    asm("{ .reg .u64 t; cvta.to.shared.u64 t, %1; cvt.u32.u64 %0, t; }" : "=r"(a) : "l"(p));
    return a;
}
__device__ __forceinline__ void mma16(float* d, const uint32_t* a, const uint32_t* b) {
    asm volatile(
        "mma.sync.aligned.m16n8k16.row.col.f32.f16.f16.f32 "
        "{%0,%1,%2,%3}, {%4,%5,%6,%7}, {%8,%9}, {%0,%1,%2,%3};"
        : "+f"(d[0]), "+f"(d[1]), "+f"(d[2]), "+f"(d[3])
        : "r"(a[0]), "r"(a[1]), "r"(a[2]), "r"(a[3]), "r"(b[0]), "r"(b[1]));
}
__device__ __forceinline__ void ldsm4(uint32_t& r0, uint32_t& r1, uint32_t& r2, uint32_t& r3,
                                      uint32_t addr) {
    asm volatile("ldmatrix.sync.aligned.m8n8.x4.shared.b16 {%0,%1,%2,%3}, [%4];"
                 : "=r"(r0), "=r"(r1), "=r"(r2), "=r"(r3) : "r"(addr));
}

template <int CFG>
__global__ void __launch_bounds__(256)
gemm_tc(const float* __restrict__ pbias, const float* __restrict__ paux,
        float* __restrict__ pout,
        const float* __restrict__ pbias2, const float* __restrict__ pqkw,
        const float* __restrict__ pqkb) {
    constexpr int K  = (CFG == 1) ? 1024
                     : (CFG == 4) ? 256
                     : (CFG == 5 || CFG == 7) ? 128 : 2048;
    constexpr int NC = (CFG == 5) ? 12 : K / 32;

    extern __shared__ char smem[];
    uint32_t sbase = smem_u32(smem);
    float* smf = (float*)smem;
    float* sb  = smf + 128 * 132;           // 256-entry T5 bias LUT (CFG7)

    int tid = threadIdx.x, w = tid >> 5, lane = tid & 31;
    int grpL = lane >> 2, tig = lane & 3;
    int wm = w >> 2, wn = w & 3;            // 2 x 4 warp grid
    int z = blockIdx.z;
    int n0 = blockIdx.x * 128, m0 = blockIdx.y * 128;
    int q = lane >> 3, rL = lane & 7;

    const __half* At; const __half* Bt;
    const __half* A2t = nullptr; const __half* B2t = nullptr;
    int lda, ldb, lda2 = 0, ldb2 = 0;
    if constexpr (CFG == 1) {
        At = g_normedH + (size_t)m0 * K; lda = K;
        Bt = (n0 >= HV2) ? g_WqkTH + (size_t)(n0 - HV2) * K
                         : g_WhTH + (size_t)n0 * K;
        ldb = K;
    } else if constexpr (CFG == 7) {
        At = g_qqH  + (size_t)z * G * QK + (size_t)m0 * QK; lda = QK;
        Bt = g_qkhH + (size_t)z * G * QK + (size_t)n0 * QK; ldb = QK;
    } else if constexpr (CFG == 4) {
        At = g_vTH  + (size_t)z * HID * G + (size_t)m0 * G; lda = G;
        Bt = g_lkTH + (size_t)z * QK * G  + (size_t)n0 * G; ldb = G;
    } else if constexpr (CFG == 5) {
        At  = g_attnH  + (size_t)z * G * G    + (size_t)m0 * G;  lda  = G;
        Bt  = g_vTH    + (size_t)z * HID * G  + (size_t)n0 * G;  ldb  = G;
        A2t = g_lqH    + (size_t)z * G * QK   + (size_t)m0 * QK; lda2 = QK;
        B2t = g_linkvH + (size_t)z * HID * QK + (size_t)n0 * QK; ldb2 = QK;
    } else {
        At = g_aoH    + (size_t)m0 * K; lda = K;
        Bt = g_WoutTH + (size_t)n0 * K; ldb = K;
    }

    float acc[4][4][4];
#pragma unroll
    for (int i = 0; i < 4; i++)
#pragma unroll
        for (int j = 0; j < 4; j++)
#pragma unroll
            for (int r = 0; r < 4; r++) acc[i][j][r] = 0.f;

    int ldrb = tid >> 2, ldcb = (tid & 3) * 8;        // global->smem mapping
    uint32_t laneA = (uint32_t)(((wm * 64 + (q & 1) * 8 + rL) * 40 + (q >> 1) * 8) * 2);
    uint32_t laneB = (uint32_t)(((wn * 32 + (q >> 1) * 8 + rL) * 40 + (q & 1) * 8) * 2) + STGB;

    auto issue = [&](int cc, int st) {
        const __half* Ap; const __half* Bp; int la, lb, c2 = cc;
        if (CFG == 5 && cc >= 8) { Ap = A2t; Bp = B2t; la = lda2; lb = ldb2; c2 = cc - 8; }
        else                     { Ap = At;  Bp = Bt;  la = lda;  lb = ldb; }
#pragma unroll
        for (int jj = 0; jj < 2; ++jj) {
            int r = ldrb + jj * 64;
            uint32_t da = sbase + (uint32_t)(st * 2 * STGB + (r * 40 + ldcb) * 2);
            asm volatile("cp.async.cg.shared.global [%0], [%1], 16;"
                         :: "r"(da), "l"(Ap + (size_t)r * la + c2 * 32 + ldcb));
            asm volatile("cp.async.cg.shared.global [%0], [%1], 16;"
                         :: "r"(da + STGB), "l"(Bp + (size_t)r * lb + c2 * 32 + ldcb));
        }
    };

    issue(0, 0);
    asm volatile("cp.async.commit_group;");
    for (int c = 0; c < NC; ++c) {
        if (c + 1 < NC) {
            issue(c + 1, (c + 1) & 1);
            asm volatile("cp.async.commit_group;");
            asm volatile("cp.async.wait_group 1;");
        } else {
            asm volatile("cp.async.wait_group 0;");
        }
        __syncthreads();
        uint32_t abase = sbase + (uint32_t)((c & 1) * 2 * STGB) + laneA;
        uint32_t bbase = sbase + (uint32_t)((c & 1) * 2 * STGB) + laneB;
#pragma unroll
        for (int s = 0; s < 2; ++s) {
            uint32_t af[4][4], bff[4][2];
#pragma unroll
            for (int i = 0; i < 4; ++i)
                ldsm4(af[i][0], af[i][1], af[i][2], af[i][3],
                      abase + (uint32_t)(i * 1280 + s * 32));
            ldsm4(bff[0][0], bff[0][1], bff[1][0], bff[1][1], bbase + (uint32_t)(s * 32));
            ldsm4(bff[2][0], bff[2][1], bff[3][0], bff[3][1],
                  bbase + (uint32_t)(1280 + s * 32));
#pragma unroll
            for (int i = 0; i < 4; ++i)
#pragma unroll
                for (int j = 0; j < 4; ++j)
                    mma16(acc[i][j], af[i], bff[j]);
        }
        __syncthreads();
    }

    // ---- stage accumulators into smem [128][132]; CFG7 also builds bias LUT ----
    if (CFG == 7) {
        int n = tid;
        int bucket;
        if (n <= 0)      bucket = 0;
        else if (n < 16) bucket = n;
        else {
            bucket = 16 + (int)(logf((float)n * (1.0f / 16.0f)) * 0.48089834696298783f * 16.0f);
            if (bucket > 31) bucket = 31;
        }
        sb[tid] = paux[bucket] * 11.313708498984761f;   // * sqrt(128)
    }
#pragma unroll
    for (int i = 0; i < 4; ++i) {
#pragma unroll
        for (int j = 0; j < 4; ++j) {
            int row = wm * 64 + i * 16 + grpL;
            int col = wn * 32 + j * 8 + tig * 2;
            smf[row * 132 + col]           = acc[i][j][0];
            smf[row * 132 + col + 1]       = acc[i][j][1];
            smf[(row + 8) * 132 + col]     = acc[i][j][2];
            smf[(row + 8) * 132 + col + 1] = acc[i][j][3];
        }
    }
    __syncthreads();

    // ---- epilogue / global write ----
    if (CFG == 1 && n0 < HID) {
        // v branch: write transposed into g_vTH[grp][gn][t]
        int grp = m0 >> 8, tg0 = m0 & 255;
#pragma unroll
        for (int it = 0; it < 16; ++it) {
            int cc = it * 8 + w;
            int gn = n0 + cc;
            float bias = pbias[gn];
            int t = lane * 4;
            uint2 o;
            o.x = pack2h(silu(smf[(t + 0) * 132 + cc] + bias),
                         silu(smf[(t + 1) * 132 + cc] + bias));
            o.y = pack2h(silu(smf[(t + 2) * 132 + cc] + bias),
                         silu(smf[(t + 3) * 132 + cc] + bias));
            *(uint2*)&g_vTH[((size_t)grp * HID + gn) * G + tg0 + t] = o;
        }
        return;
    }
    if (CFG == 1 && n0 >= HV2) {
        // qk heads: s = silu(acc + bqk); qq/lq/qkh fp16 row-major + lkT fp16 transposed
        int grp = m0 >> 8, tg0 = m0 & 255;
#pragma unroll
        for (int it = 0; it < 16; ++it) {
            int idx = tid + it * 256;
            int r = idx >> 5, c4 = (idx & 31) * 4;
            int tok = m0 + r;
            float4 bq = *(const float4*)&pbias2[c4];
            float4 s;
            s.x = silu(smf[r * 132 + c4 + 0] + bq.x);
            s.y = silu(smf[r * 132 + c4 + 1] + bq.y);
            s.z = silu(smf[r * 132 + c4 + 2] + bq.z);
            s.w = silu(smf[r * 132 + c4 + 3] + bq.w);
            smf[r * 132 + c4 + 0] = s.x; smf[r * 132 + c4 + 1] = s.y;
            smf[r * 132 + c4 + 2] = s.z; smf[r * 132 + c4 + 3] = s.w;
            float4 w0 = *(const float4*)&pqkw[c4];
            float4 b0 = *(const float4*)&pqkb[c4];
            uint2 o0;
            o0.x = pack2h(s.x * w0.x + b0.x, s.y * w0.y + b0.y);
            o0.y = pack2h(s.z * w0.z + b0.z, s.w * w0.w + b0.w);
            *(uint2*)&g_qqH[(size_t)tok * QK + c4] = o0;
            float4 w1 = *(const float4*)&pqkw[QK + c4];
            float4 b1 = *(const float4*)&pqkb[QK + c4];
            uint2 o1;
            o1.x = pack2h(s.x * w1.x + b1.x, s.y * w1.y + b1.y);
            o1.y = pack2h(s.z * w1.z + b1.z, s.w * w1.w + b1.w);
            *(uint2*)&g_lqH[(size_t)tok * QK + c4] = o1;
            float4 w2 = *(const float4*)&pqkw[2 * QK + c4];
            float4 b2 = *(const float4*)&pqkb[2 * QK + c4];
            uint2 o2;
            o2.x = pack2h(s.x * w2.x + b2.x, s.y * w2.y + b2.y);
            o2.y = pack2h(s.z * w2.z + b2.z, s.w * w2.w + b2.w);
            *(uint2*)&g_qkhH[(size_t)tok * QK + c4] = o2;
        }
        __syncthreads();
#pragma unroll
        for (int it = 0; it < 16; ++it) {
            int cc = it * 8 + w;
            float w3 = pqkw[3 * QK + cc], b3 = pqkb[3 * QK + cc];
            int t = lane * 4;
            uint2 o;
            o.x = pack2h(smf[(t + 0) * 132 + cc] * w3 + b3,
                         smf[(t + 1) * 132 + cc] * w3 + b3);
            o.y = pack2h(smf[(t + 2) * 132 + cc] * w3 + b3,
                         smf[(t + 3) * 132 + cc] * w3 + b3);
            *(uint2*)&g_lkTH[((size_t)grp * QK + cc) * G + tg0 + t] = o;
        }
        return;
    }
#pragma unroll
    for (int it = 0; it < 16; ++it) {
        int idx = tid + it * 256;              // 4096 x 4-elem slots
        int r = idx >> 5, c4 = (idx & 31) * 4;
        int gm = m0 + r, gn = n0 + c4;
        float v0 = smf[r * 132 + c4 + 0];
        float v1 = smf[r * 132 + c4 + 1];
        float v2 = smf[r * 132 + c4 + 2];
        float v3 = smf[r * 132 + c4 + 3];
        if (CFG == 1) {                        // gate branch (2048 <= n0 < 4096): fp32
            float4 o;
            o.x = silu(v0 + pbias[gn + 0]); o.y = silu(v1 + pbias[gn + 1]);
            o.z = silu(v2 + pbias[gn + 2]); o.w = silu(v3 + pbias[gn + 3]);
            *(float4*)&g_gate[(size_t)gm * HID + (gn - HID)] = o;
        } else if (CFG == 7) {                 // attention scores -> fp16
            float o4[4] = {v0, v1, v2, v3};
            float r4[4];
#pragma unroll
            for (int jj = 0; jj < 4; ++jj) {
                int d = gm - (gn + jj);
                float a = 0.f;
                if (d >= 0) {
                    float sim = o4[jj] * (1.0f / G) + sb[d];
                    a = sim > 0.f ? sim * sim : 0.f;
                }
                r4[jj] = a;
            }
            uint2 o;
            o.x = pack2h(r4[0], r4[1]); o.y = pack2h(r4[2], r4[3]);
            *(uint2*)&g_attnH[(size_t)z * (G * G) + (size_t)gm * G + gn] = o;
        } else if (CFG == 4) {                 // lin_kv -> fp16 (cumsum later)
            uint2 o;
            o.x = pack2h(v0 * (1.0f / G), v1 * (1.0f / G));
            o.y = pack2h(v2 * (1.0f / G), v3 * (1.0f / G));
            *(uint2*)&g_linkvH[((size_t)z * HID + gm) * QK + gn] = o;
        } else if (CFG == 5) {                 // merged quad+lin, gated -> fp16 (CFG6 A)
            size_t i0 = ((size_t)z * G + gm) * HID + gn;
            float4 gt = *(const float4*)&g_gate[i0];
            uint2 o;
            o.x = pack2h(v0 * gt.x, v1 * gt.y);
            o.y = pack2h(v2 * gt.z, v3 * gt.w);
            *(uint2*)&g_aoH[i0] = o;
        } else {                               // CFG 6: fp32 output
            size_t i0 = (size_t)gm * DIM + gn;
            float4 xr = *(const float4*)&paux[i0];
            float4 o;
            o.x = v0 + pbias[gn + 0] + xr.x; o.y = v1 + pbias[gn + 1] + xr.y;
            o.z = v2 + pbias[gn + 2] + xr.z; o.w = v3 + pbias[gn + 3] + xr.w;
            *(float4*)&pout[i0] = o;
        }
    }
}

// ---------------- launch ----------------
extern "C" void kernel_launch(void* const* d_in, const int* in_sizes, int n_in,
                              void* d_out, int out_size) {
    const float* x    = (const float*)d_in[0];
    const float* ln_w = (const float*)d_in[1];
    const float* ln_b = (const float*)d_in[2];
    const float* Wh   = (const float*)d_in[3];
    const float* bh   = (const float*)d_in[4];
    const float* Wqk  = (const float*)d_in[5];
    const float* bqk  = (const float*)d_in[6];
    const float* qk_w = (const float*)d_in[7];
    const float* qk_b = (const float*)d_in[8];
    const float* rel  = (const float*)d_in[9];
    const float* Wout = (const float*)d_in[10];
    const float* bout = (const float*)d_in[11];
    float* out = (float*)d_out;

    cudaFuncSetAttribute(gemm_tc<1>, cudaFuncAttributeMaxDynamicSharedMemorySize, GEMM_SMEM);
    cudaFuncSetAttribute(gemm_tc<4>, cudaFuncAttributeMaxDynamicSharedMemorySize, GEMM_SMEM);
    cudaFuncSetAttribute(gemm_tc<5>, cudaFuncAttributeMaxDynamicSharedMemorySize, GEMM_SMEM);
    cudaFuncSetAttribute(gemm_tc<6>, cudaFuncAttributeMaxDynamicSharedMemorySize, GEMM_SMEM);
    cudaFuncSetAttribute(gemm_tc<7>, cudaFuncAttributeMaxDynamicSharedMemorySize, GEMM_SMEM);

    __half* WhT;   cudaGetSymbolAddress((void**)&WhT,   g_WhTH);
    __half* WqkT;  cudaGetSymbolAddress((void**)&WqkT,  g_WqkTH);
    __half* WoutT; cudaGetSymbolAddress((void**)&WoutT, g_WoutTH);

    // weight transposes -> fp16 K-major
    transpose_h<<<dim3(HV2 / 32, DIM / 32), dim3(32, 8)>>>(Wh,   WhT,   DIM, HV2);
    transpose_h<<<dim3(QK  / 32, DIM / 32), dim3(32, 8)>>>(Wqk,  WqkT,  DIM, QK);
    transpose_h<<<dim3(DIM / 32, HID / 32), dim3(32, 8)>>>(Wout, WoutT, HID, DIM);

    // 1) LayerNorm -> fp16
    ln_kernel<<<NTOK, 256>>>(x, ln_w, ln_b);

    // 2) fused fp16 GEMM: hv = silu(normed @ [Wh|Wqk] + [bh|bqk]) -> vT + gate + qk heads
    gemm_tc<1><<<dim3(HV2 / 128 + 1, NTOK / 128, 1), 256, GEMM_SMEM>>>(
        bh, nullptr, nullptr, bqk, qk_w, qk_b);

    // 3) attn scores: relu^2(qq@qkh^T / G + T5 bias), causal
    gemm_tc<7><<<dim3(G / 128, G / 128, NGRP), 256, GEMM_SMEM>>>(
        nullptr, rel, nullptr, nullptr, nullptr, nullptr);

    // 4) lin_kv = v^T @ lin_k / g
    gemm_tc<4><<<dim3(1, HID / 128, NGRP), 256, GEMM_SMEM>>>(
        nullptr, nullptr, nullptr, nullptr, nullptr, nullptr);

    // 5) exclusive group cumsum
    cumsum_kernel<<<(NB * QK * HID) / 256, 256>>>();

    // 6) merged: ao = gate * (attn@v + lin_q@lin_kv) -> fp16
    gemm_tc<5><<<dim3(HID / 128, G / 128, NGRP), 256, GEMM_SMEM>>>(
        nullptr, nullptr, nullptr, nullptr, nullptr, nullptr);

    // 7) out = ao @ Wout + bout + x
    gemm_tc<6><<<dim3(DIM / 128, NTOK / 128, 1), 256, GEMM_SMEM>>>(
        bout, x, out, nullptr, nullptr, nullptr);
}

// round 17
// speedup vs baseline: 1.6282x; 1.0427x over previous
#include <cuda_runtime.h>
#include <cuda_fp16.h>
#include <math.h>
#include <stdint.h>

// ---------------- problem constants ----------------
#define NTOK   16384        // 4 * 4096
#define DIM    1024
#define HID    2048
#define HV2    4096         // 2*HID
#define QK     128
#define G      256
#define NGRP   64           // 4 batches * 16 groups
#define NB     4
#define NGPB   16
#define LN_EPS 1e-5f

// ---------------- scratch (device globals; all GEMM operands fp16) ----------------
__device__ __half g_normedH[(size_t)NTOK * DIM];
__device__ __half g_WhTH   [(size_t)HV2 * DIM];
__device__ __half g_WqkTH  [(size_t)QK * DIM];
__device__ __half g_WoutTH [(size_t)DIM * HID];
__device__ __half g_aoH    [(size_t)NTOK * HID];
__device__ __half g_vTH    [(size_t)NGRP * HID * G];   // v transposed: [g][e][t]
__device__ __half g_qqH    [(size_t)NTOK * QK];
__device__ __half g_lqH    [(size_t)NTOK * QK];
__device__ __half g_qkhH   [(size_t)NTOK * QK];
__device__ __half g_lkTH   [(size_t)NGRP * QK * G];    // lin_k transposed: [g][d][t]
__device__ __half g_attnH  [(size_t)NGRP * G * G];
__device__ __half g_linkvH [(size_t)NGRP * HID * QK];  // [g][e][d]
__device__ __half g_gateH  [(size_t)NTOK * HID];       // fp16 (epilogue-only consumer)

__device__ __forceinline__ float silu(float x) { return x / (1.0f + expf(-x)); }
__device__ __forceinline__ uint32_t pack2h(float a, float b) {
    __half2 h = __floats2half2_rn(a, b);
    return *(uint32_t*)&h;
}

// ---------------- LayerNorm (UNCHANGED: clock canary) ----------------
__global__ void ln_kernel(const float* __restrict__ x,
                          const float* __restrict__ w,
                          const float* __restrict__ b) {
    int row = blockIdx.x;
    const float* xr = x + (size_t)row * DIM;
    float s = 0.f, s2 = 0.f;
    for (int i = threadIdx.x; i < DIM; i += blockDim.x) {
        float v = xr[i]; s += v; s2 += v * v;
    }
    __shared__ float sh[8], sh2[8];
    for (int o = 16; o > 0; o >>= 1) {
        s  += __shfl_down_sync(0xffffffffu, s, o);
        s2 += __shfl_down_sync(0xffffffffu, s2, o);
    }
    int wid = threadIdx.x >> 5, lane = threadIdx.x & 31;
    if (lane == 0) { sh[wid] = s; sh2[wid] = s2; }
    __syncthreads();
    if (threadIdx.x == 0) {
        float a = 0.f, a2 = 0.f;
        for (int i = 0; i < (int)(blockDim.x >> 5); i++) { a += sh[i]; a2 += sh2[i]; }
        sh[0] = a; sh2[0] = a2;
    }
    __syncthreads();
    float mu  = sh[0] * (1.0f / DIM);
    float var = sh2[0] * (1.0f / DIM) - mu * mu;
    float inv = rsqrtf(var + LN_EPS);
    __half* o = g_normedH + (size_t)row * DIM;
    for (int i = threadIdx.x; i < DIM; i += blockDim.x)
        o[i] = __float2half_rn((xr[i] - mu) * inv * w[i] + b[i]);
}

// ---------------- tiled transpose -> fp16: in[R][C] -> out[C][R] ----------------
__global__ void transpose_h(const float* __restrict__ in, __half* __restrict__ out,
                            int R, int C) {
    __shared__ float t[32][33];
    int c0 = blockIdx.x * 32, r0 = blockIdx.y * 32;
    int x = threadIdx.x, y = threadIdx.y;
#pragma unroll
    for (int j = 0; j < 32; j += 8)
        t[y + j][x] = in[(size_t)(r0 + y + j) * C + c0 + x];
    __syncthreads();
#pragma unroll
    for (int j = 0; j < 32; j += 8)
        out[(size_t)(c0 + y + j) * R + r0 + x] = __float2half_rn(t[x][y + j]);
}

// ---------------- exclusive group cumsum of lin_kv (fp32 accumulate, fp16 store) ----------------
__global__ void cumsum_kernel() {
    int p = blockIdx.x * blockDim.x + threadIdx.x;
    if (p >= NB * QK * HID) return;
    int b = p / (QK * HID);
    int off = p - b * (QK * HID);
    float acc = 0.f;
#pragma unroll
    for (int g = 0; g < NGPB; g++) {
        size_t idx = (size_t)(b * NGPB + g) * (QK * HID) + off;
        float t = __half2float(g_linkvH[idx]);
        g_linkvH[idx] = __float2half_rn(acc);
        acc += t;
    }
}

// ---------------- fp16 mma.sync GEMM, 128x128 CTA tile, K-chunk 32, 2-stage, LDSM ----------------
// Single-barrier mainloop: wait_group 0 -> sync -> prefetch(c+1) -> compute(c).
// CFG 1: A=g_normedH, B=g_WhTH (x<32) / g_WqkTH (x==32), M=16384, K=1024
// CFG 7: qq@qkh^T; /G + T5 bias + relu^2 + mask -> attnH
// CFG 4: vT@lkT / 256 -> linkvH
// CFG 5 (merged): attn@vT (K=256) + lq@linkv (K=128); aoH = fp16(acc*gate)
// CFG 6: aoH @ WoutTH, K=2048; +bout+x -> out (fp32)
#define STGB    10240                       // fp16 operand stage (128x40 halves)
#define GEMM_SMEM 69632                     // epilogue smf[128][132] f32 + 1KB LUT

__device__ __forceinline__ uint32_t smem_u32(const void* p) {
    uint32_t a;
    asm("{ .reg .u64 t; cvta.to.shared.u64 t, %1; cvt.u32.u64 %0, t; }" : "=r"(a) : "l"(p));
    return a;
}
__device__ __forceinline__ void mma16(float* d, const uint32_t* a, const uint32_t* b) {
    asm volatile(
        "mma.sync.aligned.m16n8k16.row.col.f32.f16.f16.f32 "
        "{%0,%1,%2,%3}, {%4,%5,%6,%7}, {%8,%9}, {%0,%1,%2,%3};"
        : "+f"(d[0]), "+f"(d[1]), "+f"(d[2]), "+f"(d[3])
        : "r"(a[0]), "r"(a[1]), "r"(a[2]), "r"(a[3]), "r"(b[0]), "r"(b[1]));
}
__device__ __forceinline__ void ldsm4(uint32_t& r0, uint32_t& r1, uint32_t& r2, uint32_t& r3,
                                      uint32_t addr) {
    asm volatile("ldmatrix.sync.aligned.m8n8.x4.shared.b16 {%0,%1,%2,%3}, [%4];"
                 : "=r"(r0), "=r"(r1), "=r"(r2), "=r"(r3) : "r"(addr));
}

template <int CFG>
__global__ void __launch_bounds__(256)
gemm_tc(const float* __restrict__ pbias, const float* __restrict__ paux,
        float* __restrict__ pout,
        const float* __restrict__ pbias2, const float* __restrict__ pqkw,
        const float* __restrict__ pqkb) {
    constexpr int K  = (CFG == 1) ? 1024
                     : (CFG == 4) ? 256
                     : (CFG == 5 || CFG == 7) ? 128 : 2048;
    constexpr int NC = (CFG == 5) ? 12 : K / 32;

    extern __shared__ char smem[];
    uint32_t sbase = smem_u32(smem);
    float* smf = (float*)smem;
    float* sb  = smf + 128 * 132;           // 256-entry T5 bias LUT (CFG7)

    int tid = threadIdx.x, w = tid >> 5, lane = tid & 31;
    int grpL = lane >> 2, tig = lane & 3;
    int wm = w >> 2, wn = w & 3;            // 2 x 4 warp grid
    int z = blockIdx.z;
    int n0 = blockIdx.x * 128, m0 = blockIdx.y * 128;
    int q = lane >> 3, rL = lane & 7;

    const __half* At; const __half* Bt;
    const __half* A2t = nullptr; const __half* B2t = nullptr;
    int lda, ldb, lda2 = 0, ldb2 = 0;
    if constexpr (CFG == 1) {
        At = g_normedH + (size_t)m0 * K; lda = K;
        Bt = (n0 >= HV2) ? g_WqkTH + (size_t)(n0 - HV2) * K
                         : g_WhTH + (size_t)n0 * K;
        ldb = K;
    } else if constexpr (CFG == 7) {
        At = g_qqH  + (size_t)z * G * QK + (size_t)m0 * QK; lda = QK;
        Bt = g_qkhH + (size_t)z * G * QK + (size_t)n0 * QK; ldb = QK;
    } else if constexpr (CFG == 4) {
        At = g_vTH  + (size_t)z * HID * G + (size_t)m0 * G; lda = G;
        Bt = g_lkTH + (size_t)z * QK * G  + (size_t)n0 * G; ldb = G;
    } else if constexpr (CFG == 5) {
        At  = g_attnH  + (size_t)z * G * G    + (size_t)m0 * G;  lda  = G;
        Bt  = g_vTH    + (size_t)z * HID * G  + (size_t)n0 * G;  ldb  = G;
        A2t = g_lqH    + (size_t)z * G * QK   + (size_t)m0 * QK; lda2 = QK;
        B2t = g_linkvH + (size_t)z * HID * QK + (size_t)n0 * QK; ldb2 = QK;
    } else {
        At = g_aoH    + (size_t)m0 * K; lda = K;
        Bt = g_WoutTH + (size_t)n0 * K; ldb = K;
    }

    float acc[4][4][4];
#pragma unroll
    for (int i = 0; i < 4; i++)
#pragma unroll
        for (int j = 0; j < 4; j++)
#pragma unroll
            for (int r = 0; r < 4; r++) acc[i][j][r] = 0.f;

    int ldrb = tid >> 2, ldcb = (tid & 3) * 8;        // global->smem mapping
    uint32_t laneA = (uint32_t)(((wm * 64 + (q & 1) * 8 + rL) * 40 + (q >> 1) * 8) * 2);
    uint32_t laneB = (uint32_t)(((wn * 32 + (q >> 1) * 8 + rL) * 40 + (q & 1) * 8) * 2) + STGB;

    auto issue = [&](int cc, int st) {
        const __half* Ap; const __half* Bp; int la, lb, c2 = cc;
        if (CFG == 5 && cc >= 8) { Ap = A2t; Bp = B2t; la = lda2; lb = ldb2; c2 = cc - 8; }
        else                     { Ap = At;  Bp = Bt;  la = lda;  lb = ldb; }
#pragma unroll
        for (int jj = 0; jj < 2; ++jj) {
            int r = ldrb + jj * 64;
            uint32_t da = sbase + (uint32_t)(st * 2 * STGB + (r * 40 + ldcb) * 2);
            asm volatile("cp.async.cg.shared.global [%0], [%1], 16;"
                         :: "r"(da), "l"(Ap + (size_t)r * la + c2 * 32 + ldcb));
            asm volatile("cp.async.cg.shared.global [%0], [%1], 16;"
                         :: "r"(da + STGB), "l"(Bp + (size_t)r * lb + c2 * 32 + ldcb));
        }
    };

    issue(0, 0);
    asm volatile("cp.async.commit_group;");
    for (int c = 0; c < NC; ++c) {
        asm volatile("cp.async.wait_group 0;");
        __syncthreads();                    // data c visible; all warps done reading stage (c+1)&1
        if (c + 1 < NC) {
            issue(c + 1, (c + 1) & 1);
            asm volatile("cp.async.commit_group;");
        }
        uint32_t abase = sbase + (uint32_t)((c & 1) * 2 * STGB) + laneA;
        uint32_t bbase = sbase + (uint32_t)((c & 1) * 2 * STGB) + laneB;
#pragma unroll
        for (int s = 0; s < 2; ++s) {
            uint32_t af[4][4], bff[4][2];
#pragma unroll
            for (int i = 0; i < 4; ++i)
                ldsm4(af[i][0], af[i][1], af[i][2], af[i][3],
                      abase + (uint32_t)(i * 1280 + s * 32));
            ldsm4(bff[0][0], bff[0][1], bff[1][0], bff[1][1], bbase + (uint32_t)(s * 32));
            ldsm4(bff[2][0], bff[2][1], bff[3][0], bff[3][1],
                  bbase + (uint32_t)(1280 + s * 32));
#pragma unroll
            for (int i = 0; i < 4; ++i)
#pragma unroll
                for (int j = 0; j < 4; ++j)
                    mma16(acc[i][j], af[i], bff[j]);
        }
    }
    __syncthreads();                        // all reads done before smf overwrites operands

    // ---- stage accumulators into smem [128][132]; CFG7 also builds bias LUT ----
    if (CFG == 7) {
        int n = tid;
        int bucket;
        if (n <= 0)      bucket = 0;
        else if (n < 16) bucket = n;
        else {
            bucket = 16 + (int)(logf((float)n * (1.0f / 16.0f)) * 0.48089834696298783f * 16.0f);
            if (bucket > 31) bucket = 31;
        }
        sb[tid] = paux[bucket] * 11.313708498984761f;   // * sqrt(128)
    }
#pragma unroll
    for (int i = 0; i < 4; ++i) {
#pragma unroll
        for (int j = 0; j < 4; ++j) {
            int row = wm * 64 + i * 16 + grpL;
            int col = wn * 32 + j * 8 + tig * 2;
            smf[row * 132 + col]           = acc[i][j][0];
            smf[row * 132 + col + 1]       = acc[i][j][1];
            smf[(row + 8) * 132 + col]     = acc[i][j][2];
            smf[(row + 8) * 132 + col + 1] = acc[i][j][3];
        }
    }
    __syncthreads();

    // ---- epilogue / global write ----
    if (CFG == 1 && n0 < HID) {
        // v branch: write transposed into g_vTH[grp][gn][t]
        int grp = m0 >> 8, tg0 = m0 & 255;
#pragma unroll
        for (int it = 0; it < 16; ++it) {
            int cc = it * 8 + w;
            int gn = n0 + cc;
            float bias = pbias[gn];
            int t = lane * 4;
            uint2 o;
            o.x = pack2h(silu(smf[(t + 0) * 132 + cc] + bias),
                         silu(smf[(t + 1) * 132 + cc] + bias));
            o.y = pack2h(silu(smf[(t + 2) * 132 + cc] + bias),
                         silu(smf[(t + 3) * 132 + cc] + bias));
            *(uint2*)&g_vTH[((size_t)grp * HID + gn) * G + tg0 + t] = o;
        }
        return;
    }
    if (CFG == 1 && n0 >= HV2) {
        // qk heads: s = silu(acc + bqk); qq/lq/qkh fp16 row-major + lkT fp16 transposed
        int grp = m0 >> 8, tg0 = m0 & 255;
#pragma unroll
        for (int it = 0; it < 16; ++it) {
            int idx = tid + it * 256;
            int r = idx >> 5, c4 = (idx & 31) * 4;
            int tok = m0 + r;
            float4 bq = *(const float4*)&pbias2[c4];
            float4 s;
            s.x = silu(smf[r * 132 + c4 + 0] + bq.x);
            s.y = silu(smf[r * 132 + c4 + 1] + bq.y);
            s.z = silu(smf[r * 132 + c4 + 2] + bq.z);
            s.w = silu(smf[r * 132 + c4 + 3] + bq.w);
            smf[r * 132 + c4 + 0] = s.x; smf[r * 132 + c4 + 1] = s.y;
            smf[r * 132 + c4 + 2] = s.z; smf[r * 132 + c4 + 3] = s.w;
            float4 w0 = *(const float4*)&pqkw[c4];
            float4 b0 = *(const float4*)&pqkb[c4];
            uint2 o0;
            o0.x = pack2h(s.x * w0.x + b0.x, s.y * w0.y + b0.y);
            o0.y = pack2h(s.z * w0.z + b0.z, s.w * w0.w + b0.w);
            *(uint2*)&g_qqH[(size_t)tok * QK + c4] = o0;
            float4 w1 = *(const float4*)&pqkw[QK + c4];
            float4 b1 = *(const float4*)&pqkb[QK + c4];
            uint2 o1;
            o1.x = pack2h(s.x * w1.x + b1.x, s.y * w1.y + b1.y);
            o1.y = pack2h(s.z * w1.z + b1.z, s.w * w1.w + b1.w);
            *(uint2*)&g_lqH[(size_t)tok * QK + c4] = o1;
            float4 w2 = *(const float4*)&pqkw[2 * QK + c4];
            float4 b2 = *(const float4*)&pqkb[2 * QK + c4];
            uint2 o2;
            o2.x = pack2h(s.x * w2.x + b2.x, s.y * w2.y + b2.y);
            o2.y = pack2h(s.z * w2.z + b2.z, s.w * w2.w + b2.w);
            *(uint2*)&g_qkhH[(size_t)tok * QK + c4] = o2;
        }
        __syncthreads();
#pragma unroll
        for (int it = 0; it < 16; ++it) {
            int cc = it * 8 + w;
            float w3 = pqkw[3 * QK + cc], b3 = pqkb[3 * QK + cc];
            int t = lane * 4;
            uint2 o;
            o.x = pack2h(smf[(t + 0) * 132 + cc] * w3 + b3,
                         smf[(t + 1) * 132 + cc] * w3 + b3);
            o.y = pack2h(smf[(t + 2) * 132 + cc] * w3 + b3,
                         smf[(t + 3) * 132 + cc] * w3 + b3);
            *(uint2*)&g_lkTH[((size_t)grp * QK + cc) * G + tg0 + t] = o;
        }
        return;
    }
#pragma unroll
    for (int it = 0; it < 16; ++it) {
        int idx = tid + it * 256;              // 4096 x 4-elem slots
        int r = idx >> 5, c4 = (idx & 31) * 4;
        int gm = m0 + r, gn = n0 + c4;
        float v0 = smf[r * 132 + c4 + 0];
        float v1 = smf[r * 132 + c4 + 1];
        float v2 = smf[r * 132 + c4 + 2];
        float v3 = smf[r * 132 + c4 + 3];
        if (CFG == 1) {                        // gate branch (2048 <= n0 < 4096): fp16
            uint2 o;
            o.x = pack2h(silu(v0 + pbias[gn + 0]), silu(v1 + pbias[gn + 1]));
            o.y = pack2h(silu(v2 + pbias[gn + 2]), silu(v3 + pbias[gn + 3]));
            *(uint2*)&g_gateH[(size_t)gm * HID + (gn - HID)] = o;
        } else if (CFG == 7) {                 // attention scores -> fp16
            float o4[4] = {v0, v1, v2, v3};
            float r4[4];
#pragma unroll
            for (int jj = 0; jj < 4; ++jj) {
                int d = gm - (gn + jj);
                float a = 0.f;
                if (d >= 0) {
                    float sim = o4[jj] * (1.0f / G) + sb[d];
                    a = sim > 0.f ? sim * sim : 0.f;
                }
                r4[jj] = a;
            }
            uint2 o;
            o.x = pack2h(r4[0], r4[1]); o.y = pack2h(r4[2], r4[3]);
            *(uint2*)&g_attnH[(size_t)z * (G * G) + (size_t)gm * G + gn] = o;
        } else if (CFG == 4) {                 // lin_kv -> fp16 (cumsum later)
            uint2 o;
            o.x = pack2h(v0 * (1.0f / G), v1 * (1.0f / G));
            o.y = pack2h(v2 * (1.0f / G), v3 * (1.0f / G));
            *(uint2*)&g_linkvH[((size_t)z * HID + gm) * QK + gn] = o;
        } else if (CFG == 5) {                 // merged quad+lin, gated -> fp16 (CFG6 A)
            size_t i0 = ((size_t)z * G + gm) * HID + gn;
            __half2 h0 = *(const __half2*)&g_gateH[i0];
            __half2 h1 = *(const __half2*)&g_gateH[i0 + 2];
            float2 f0 = __half22float2(h0), f1 = __half22float2(h1);
            uint2 o;
            o.x = pack2h(v0 * f0.x, v1 * f0.y);
            o.y = pack2h(v2 * f1.x, v3 * f1.y);
            *(uint2*)&g_aoH[i0] = o;
        } else {                               // CFG 6: fp32 output
            size_t i0 = (size_t)gm * DIM + gn;
            float4 xr = *(const float4*)&paux[i0];
            float4 o;
            o.x = v0 + pbias[gn + 0] + xr.x; o.y = v1 + pbias[gn + 1] + xr.y;
            o.z = v2 + pbias[gn + 2] + xr.z; o.w = v3 + pbias[gn + 3] + xr.w;
            *(float4*)&pout[i0] = o;
        }
    }
}

// ---------------- launch ----------------
extern "C" void kernel_launch(void* const* d_in, const int* in_sizes, int n_in,
                              void* d_out, int out_size) {
    const float* x    = (const float*)d_in[0];
    const float* ln_w = (const float*)d_in[1];
    const float* ln_b = (const float*)d_in[2];
    const float* Wh   = (const float*)d_in[3];
    const float* bh   = (const float*)d_in[4];
    const float* Wqk  = (const float*)d_in[5];
    const float* bqk  = (const float*)d_in[6];
    const float* qk_w = (const float*)d_in[7];
    const float* qk_b = (const float*)d_in[8];
    const float* rel  = (const float*)d_in[9];
    const float* Wout = (const float*)d_in[10];
    const float* bout = (const float*)d_in[11];
    float* out = (float*)d_out;

    cudaFuncSetAttribute(gemm_tc<1>, cudaFuncAttributeMaxDynamicSharedMemorySize, GEMM_SMEM);
    cudaFuncSetAttribute(gemm_tc<4>, cudaFuncAttributeMaxDynamicSharedMemorySize, GEMM_SMEM);
    cudaFuncSetAttribute(gemm_tc<5>, cudaFuncAttributeMaxDynamicSharedMemorySize, GEMM_SMEM);
    cudaFuncSetAttribute(gemm_tc<6>, cudaFuncAttributeMaxDynamicSharedMemorySize, GEMM_SMEM);
    cudaFuncSetAttribute(gemm_tc<7>, cudaFuncAttributeMaxDynamicSharedMemorySize, GEMM_SMEM);

    __half* WhT;   cudaGetSymbolAddress((void**)&WhT,   g_WhTH);
    __half* WqkT;  cudaGetSymbolAddress((void**)&WqkT,  g_WqkTH);
    __half* WoutT; cudaGetSymbolAddress((void**)&WoutT, g_WoutTH);

    // weight transposes -> fp16 K-major
    transpose_h<<<dim3(HV2 / 32, DIM / 32), dim3(32, 8)>>>(Wh,   WhT,   DIM, HV2);
    transpose_h<<<dim3(QK  / 32, DIM / 32), dim3(32, 8)>>>(Wqk,  WqkT,  DIM, QK);
    transpose_h<<<dim3(DIM / 32, HID / 32), dim3(32, 8)>>>(Wout, WoutT, HID, DIM);

    // 1) LayerNorm -> fp16
    ln_kernel<<<NTOK, 256>>>(x, ln_w, ln_b);

    // 2) fused fp16 GEMM: hv = silu(normed @ [Wh|Wqk] + [bh|bqk]) -> vT + gate + qk heads
    gemm_tc<1><<<dim3(HV2 / 128 + 1, NTOK / 128, 1), 256, GEMM_SMEM>>>(
        bh, nullptr, nullptr, bqk, qk_w, qk_b);

    // 3) attn scores: relu^2(qq@qkh^T / G + T5 bias), causal
    gemm_tc<7><<<dim3(G / 128, G / 128, NGRP), 256, GEMM_SMEM>>>(
        nullptr, rel, nullptr, nullptr, nullptr, nullptr);

    // 4) lin_kv = v^T @ lin_k / g
    gemm_tc<4><<<dim3(1, HID / 128, NGRP), 256, GEMM_SMEM>>>(
        nullptr, nullptr, nullptr, nullptr, nullptr, nullptr);

    // 5) exclusive group cumsum
    cumsum_kernel<<<(NB * QK * HID) / 256, 256>>>();

    // 6) merged: ao = gate * (attn@v + lin_q@lin_kv) -> fp16
    gemm_tc<5><<<dim3(HID / 128, G / 128, NGRP), 256, GEMM_SMEM>>>(
        nullptr, nullptr, nullptr, nullptr, nullptr, nullptr);

    // 7) out = ao @ Wout + bout + x
    gemm_tc<6><<<dim3(DIM / 128, NTOK / 128, 1), 256, GEMM_SMEM>>>(
        bout, x, out, nullptr, nullptr, nullptr);
}